// round 1
// baseline (speedup 1.0000x reference)
#include <cuda_runtime.h>

#define NN 50000
#define NE 800000
#define DD 512
#define NL 3
#define LN_EPS 1e-5f

// Scratch (device globals — no allocation allowed)
__device__ float g_ht[NN * DD];    // linear output per layer
__device__ float g_agg[NN * DD];   // aggregation buffer
__device__ float g_h[NN * DD];     // hidden state between layers
__device__ float g_deg[NN];
__device__ float g_isq[NN];

// ---------------------------------------------------------------------------
// Degree computation: deg = 1 + incoming-edge count; isq = rsqrt(deg)
// ---------------------------------------------------------------------------
__global__ void k_deg_init() {
    int i = blockIdx.x * blockDim.x + threadIdx.x;
    if (i < NN) g_deg[i] = 1.0f;
}

__global__ void k_deg_accum(const int* __restrict__ dst) {
    int e = blockIdx.x * blockDim.x + threadIdx.x;
    if (e < NE) atomicAdd(&g_deg[dst[e]], 1.0f);
}

__global__ void k_isq() {
    int i = blockIdx.x * blockDim.x + threadIdx.x;
    if (i < NN) g_isq[i] = rsqrtf(g_deg[i]);
}

__global__ void k_zero_agg() {
    int i = blockIdx.x * blockDim.x + threadIdx.x;
    if (i < NN * DD / 4)
        reinterpret_cast<float4*>(g_agg)[i] = make_float4(0.f, 0.f, 0.f, 0.f);
}

// ---------------------------------------------------------------------------
// GEMM: g_ht = A @ W + bias,  A = (use_x ? x : g_h), [NN x DD] @ [DD x DD]
// Classic smem-tiled SGEMM: BM=128, BN=128, BK=16, 256 threads, 8x8/thread.
// ---------------------------------------------------------------------------
__global__ __launch_bounds__(256, 2) void k_gemm(const float* __restrict__ x, int use_x,
                                                 const float* __restrict__ W,
                                                 const float* __restrict__ bias) {
    const float* __restrict__ A = use_x ? x : (const float*)g_h;
    __shared__ float As[16][132];  // transposed A tile, padded
    __shared__ float Bs[16][128];

    int tid = threadIdx.x;
    int m0 = blockIdx.x * 128;
    int n0 = blockIdx.y * 128;
    int tr = tid >> 4;      // 0..15 (row group)
    int tc = tid & 15;      // 0..15 (col group)

    // A tile load mapping: 128 rows x 16 cols = 512 float4; 2 per thread
    int aRow = tid >> 2;    // 0..63
    int aC4  = tid & 3;     // float4 index within 16-wide row
    // B tile load mapping: 16 rows x 128 cols = 512 float4; 2 per thread
    int bRow = tid >> 5;    // 0..7
    int bC4  = tid & 31;    // 0..31

    float acc[8][8];
    #pragma unroll
    for (int i = 0; i < 8; i++)
        #pragma unroll
        for (int j = 0; j < 8; j++) acc[i][j] = 0.f;

    for (int kb = 0; kb < DD; kb += 16) {
        #pragma unroll
        for (int h = 0; h < 2; h++) {
            int r = aRow + h * 64;
            int gr = m0 + r;
            float4 v = make_float4(0.f, 0.f, 0.f, 0.f);
            if (gr < NN)
                v = *reinterpret_cast<const float4*>(&A[gr * DD + kb + aC4 * 4]);
            As[aC4 * 4 + 0][r] = v.x;
            As[aC4 * 4 + 1][r] = v.y;
            As[aC4 * 4 + 2][r] = v.z;
            As[aC4 * 4 + 3][r] = v.w;
        }
        #pragma unroll
        for (int h = 0; h < 2; h++) {
            int r = bRow + h * 8;
            float4 v = *reinterpret_cast<const float4*>(&W[(kb + r) * DD + n0 + bC4 * 4]);
            *reinterpret_cast<float4*>(&Bs[r][bC4 * 4]) = v;
        }
        __syncthreads();
        #pragma unroll
        for (int k = 0; k < 16; k++) {
            float a[8], b[8];
            #pragma unroll
            for (int i = 0; i < 8; i++) a[i] = As[k][tr * 8 + i];
            #pragma unroll
            for (int j = 0; j < 8; j++) b[j] = Bs[k][tc * 8 + j];
            #pragma unroll
            for (int i = 0; i < 8; i++)
                #pragma unroll
                for (int j = 0; j < 8; j++)
                    acc[i][j] = fmaf(a[i], b[j], acc[i][j]);
        }
        __syncthreads();
    }

    float bv[8];
    #pragma unroll
    for (int j = 0; j < 8; j++) bv[j] = bias[n0 + tc * 8 + j];

    #pragma unroll
    for (int i = 0; i < 8; i++) {
        int gr = m0 + tr * 8 + i;
        if (gr < NN) {
            float4 o0, o1;
            o0.x = acc[i][0] + bv[0]; o0.y = acc[i][1] + bv[1];
            o0.z = acc[i][2] + bv[2]; o0.w = acc[i][3] + bv[3];
            o1.x = acc[i][4] + bv[4]; o1.y = acc[i][5] + bv[5];
            o1.z = acc[i][6] + bv[6]; o1.w = acc[i][7] + bv[7];
            float4* p = reinterpret_cast<float4*>(&g_ht[gr * DD + n0 + tc * 8]);
            p[0] = o0;
            p[1] = o1;
        }
    }
}

// ---------------------------------------------------------------------------
// Edge scatter: agg[dst] += ht[src] * isq[src]*isq[dst]
// One warp per edge; 16B vector reductions (red.global.add.v4.f32, sm_90+).
// ---------------------------------------------------------------------------
__global__ void k_scatter(const int* __restrict__ src, const int* __restrict__ dst) {
    int e = blockIdx.x * 8 + (threadIdx.x >> 5);
    if (e >= NE) return;
    int lane = threadIdx.x & 31;
    int s = src[e], d = dst[e];
    float w = g_isq[s] * g_isq[d];
    const float4* ps = reinterpret_cast<const float4*>(&g_ht[s * DD]);
    float4* pd = reinterpret_cast<float4*>(&g_agg[d * DD]);
    #pragma unroll
    for (int j = 0; j < 4; j++) {
        float4 v = ps[lane + 32 * j];
        asm volatile("red.global.add.v4.f32 [%0], {%1, %2, %3, %4};" ::
                     "l"(pd + lane + 32 * j),
                     "f"(v.x * w), "f"(v.y * w), "f"(v.z * w), "f"(v.w * w)
                     : "memory");
    }
}

// ---------------------------------------------------------------------------
// Fused self-loop + LayerNorm + ReLU: h = relu(LN(agg + ht/deg)*gamma + beta)
// One warp per row (512 floats = 4 float4 per lane).
// ---------------------------------------------------------------------------
__global__ void k_ln_relu(const float* __restrict__ gamma, const float* __restrict__ beta,
                          float* __restrict__ out, int to_out) {
    int row = blockIdx.x * 8 + (threadIdx.x >> 5);
    if (row >= NN) return;
    int lane = threadIdx.x & 31;
    float invdeg = 1.0f / g_deg[row];
    const float4* pa = reinterpret_cast<const float4*>(&g_agg[row * DD]);
    const float4* ph = reinterpret_cast<const float4*>(&g_ht[row * DD]);

    float4 v[4];
    float sum = 0.f, sq = 0.f;
    #pragma unroll
    for (int j = 0; j < 4; j++) {
        float4 a = pa[lane + 32 * j];
        float4 h = ph[lane + 32 * j];
        a.x += h.x * invdeg; a.y += h.y * invdeg;
        a.z += h.z * invdeg; a.w += h.w * invdeg;
        v[j] = a;
        sum += a.x + a.y + a.z + a.w;
        sq  += a.x * a.x + a.y * a.y + a.z * a.z + a.w * a.w;
    }
    #pragma unroll
    for (int o = 16; o > 0; o >>= 1) {
        sum += __shfl_xor_sync(0xffffffffu, sum, o);
        sq  += __shfl_xor_sync(0xffffffffu, sq, o);
    }
    float mean = sum * (1.0f / DD);
    float var  = sq * (1.0f / DD) - mean * mean;
    float rstd = rsqrtf(var + LN_EPS);

    float* __restrict__ po = to_out ? out : (float*)g_h;
    #pragma unroll
    for (int j = 0; j < 4; j++) {
        int col = (lane + 32 * j) * 4;
        float4 a = v[j];
        float4 r;
        r.x = fmaxf(gamma[col + 0] * (a.x - mean) * rstd + beta[col + 0], 0.f);
        r.y = fmaxf(gamma[col + 1] * (a.y - mean) * rstd + beta[col + 1], 0.f);
        r.z = fmaxf(gamma[col + 2] * (a.z - mean) * rstd + beta[col + 2], 0.f);
        r.w = fmaxf(gamma[col + 3] * (a.w - mean) * rstd + beta[col + 3], 0.f);
        reinterpret_cast<float4*>(&po[row * DD])[lane + 32 * j] = r;
    }
}

// ---------------------------------------------------------------------------
extern "C" void kernel_launch(void* const* d_in, const int* in_sizes, int n_in,
                              void* d_out, int out_size) {
    const float* x      = (const float*)d_in[0];   // [NN, DD]
    const int*   edge   = (const int*)  d_in[1];   // [2, NE]
    const float* Ws     = (const float*)d_in[2];   // [NL, DD, DD]
    const float* bs     = (const float*)d_in[3];   // [NL, DD]
    const float* gammas = (const float*)d_in[4];   // [NL, DD]
    const float* betas  = (const float*)d_in[5];   // [NL, DD]
    float* out = (float*)d_out;

    const int* src = edge;
    const int* dst = edge + NE;

    k_deg_init<<<(NN + 255) / 256, 256>>>();
    k_deg_accum<<<(NE + 255) / 256, 256>>>(dst);
    k_isq<<<(NN + 255) / 256, 256>>>();

    dim3 ggrid((NN + 127) / 128, DD / 128);
    for (int l = 0; l < NL; l++) {
        k_gemm<<<ggrid, 256>>>(x, l == 0 ? 1 : 0, Ws + l * DD * DD, bs + l * DD);
        k_zero_agg<<<(NN * DD / 4 + 255) / 256, 256>>>();
        k_scatter<<<(NE + 7) / 8, 256>>>(src, dst);
        k_ln_relu<<<(NN + 7) / 8, 256>>>(gammas + l * DD, betas + l * DD,
                                         out, l == NL - 1 ? 1 : 0);
    }
}

// round 2
// speedup vs baseline: 1.3776x; 1.3776x over previous
#include <cuda_runtime.h>

#define NN 50000
#define NE 800000
#define DD 512
#define NL 3
#define LN_EPS 1e-5f

// Scratch (device globals — no allocation allowed)
__device__ float g_ht[NN * DD];    // linear output per layer
__device__ float g_h[NN * DD];     // hidden state between layers
__device__ float g_deg[NN];
__device__ float g_isq[NN];
__device__ int   g_row_off[NN + 1];
__device__ int   g_cursor[NN];
__device__ int   g_csr_src[NE];

// ---------------------------------------------------------------------------
// Degree: deg = 1 + incoming-edge count (float atomics give exact ints here)
// ---------------------------------------------------------------------------
__global__ void k_deg_init() {
    int i = blockIdx.x * blockDim.x + threadIdx.x;
    if (i < NN) g_deg[i] = 1.0f;
}

__global__ void k_deg_accum(const int* __restrict__ dst) {
    int e = blockIdx.x * blockDim.x + threadIdx.x;
    if (e < NE) atomicAdd(&g_deg[dst[e]], 1.0f);
}

__global__ void k_isq() {
    int i = blockIdx.x * blockDim.x + threadIdx.x;
    if (i < NN) g_isq[i] = rsqrtf(g_deg[i]);
}

// ---------------------------------------------------------------------------
// Exclusive prefix scan of in-degree counts -> CSR row offsets (+cursor copy).
// Single block, 1024 threads, each covers a contiguous chunk.
// ---------------------------------------------------------------------------
__global__ void k_scan() {
    const int T = 1024;
    const int CHUNK = (NN + T - 1) / T;  // 49
    __shared__ int s_sum[T];
    int t = threadIdx.x;
    int base = t * CHUNK;

    int local = 0;
    for (int i = 0; i < CHUNK; i++) {
        int idx = base + i;
        if (idx < NN) local += (int)(g_deg[idx] - 1.0f);
    }
    s_sum[t] = local;
    __syncthreads();
    // Hillis-Steele inclusive scan
    for (int off = 1; off < T; off <<= 1) {
        int v = (t >= off) ? s_sum[t - off] : 0;
        __syncthreads();
        s_sum[t] += v;
        __syncthreads();
    }
    int run = (t == 0) ? 0 : s_sum[t - 1];
    for (int i = 0; i < CHUNK; i++) {
        int idx = base + i;
        if (idx < NN) {
            g_row_off[idx] = run;
            g_cursor[idx]  = run;
            run += (int)(g_deg[idx] - 1.0f);
        }
    }
    if (t == T - 1) g_row_off[NN] = run;
}

__global__ void k_fill(const int* __restrict__ src, const int* __restrict__ dst) {
    int e = blockIdx.x * blockDim.x + threadIdx.x;
    if (e < NE) {
        int p = atomicAdd(&g_cursor[dst[e]], 1);
        g_csr_src[p] = src[e];
    }
}

// ---------------------------------------------------------------------------
// GEMM: g_ht = A @ W + bias,  A = (use_x ? x : g_h), [NN x DD] @ [DD x DD]
// Classic smem-tiled SGEMM: BM=128, BN=128, BK=16, 256 threads, 8x8/thread.
// ---------------------------------------------------------------------------
__global__ __launch_bounds__(256, 2) void k_gemm(const float* __restrict__ x, int use_x,
                                                 const float* __restrict__ W,
                                                 const float* __restrict__ bias) {
    const float* __restrict__ A = use_x ? x : (const float*)g_h;
    __shared__ float As[16][132];  // transposed A tile, padded
    __shared__ float Bs[16][128];

    int tid = threadIdx.x;
    int m0 = blockIdx.x * 128;
    int n0 = blockIdx.y * 128;
    int tr = tid >> 4;
    int tc = tid & 15;

    int aRow = tid >> 2;
    int aC4  = tid & 3;
    int bRow = tid >> 5;
    int bC4  = tid & 31;

    float acc[8][8];
    #pragma unroll
    for (int i = 0; i < 8; i++)
        #pragma unroll
        for (int j = 0; j < 8; j++) acc[i][j] = 0.f;

    for (int kb = 0; kb < DD; kb += 16) {
        #pragma unroll
        for (int h = 0; h < 2; h++) {
            int r = aRow + h * 64;
            int gr = m0 + r;
            float4 v = make_float4(0.f, 0.f, 0.f, 0.f);
            if (gr < NN)
                v = *reinterpret_cast<const float4*>(&A[gr * DD + kb + aC4 * 4]);
            As[aC4 * 4 + 0][r] = v.x;
            As[aC4 * 4 + 1][r] = v.y;
            As[aC4 * 4 + 2][r] = v.z;
            As[aC4 * 4 + 3][r] = v.w;
        }
        #pragma unroll
        for (int h = 0; h < 2; h++) {
            int r = bRow + h * 8;
            float4 v = *reinterpret_cast<const float4*>(&W[(kb + r) * DD + n0 + bC4 * 4]);
            *reinterpret_cast<float4*>(&Bs[r][bC4 * 4]) = v;
        }
        __syncthreads();
        #pragma unroll
        for (int k = 0; k < 16; k++) {
            float a[8], b[8];
            #pragma unroll
            for (int i = 0; i < 8; i++) a[i] = As[k][tr * 8 + i];
            #pragma unroll
            for (int j = 0; j < 8; j++) b[j] = Bs[k][tc * 8 + j];
            #pragma unroll
            for (int i = 0; i < 8; i++)
                #pragma unroll
                for (int j = 0; j < 8; j++)
                    acc[i][j] = fmaf(a[i], b[j], acc[i][j]);
        }
        __syncthreads();
    }

    float bv[8];
    #pragma unroll
    for (int j = 0; j < 8; j++) bv[j] = bias[n0 + tc * 8 + j];

    #pragma unroll
    for (int i = 0; i < 8; i++) {
        int gr = m0 + tr * 8 + i;
        if (gr < NN) {
            float4 o0, o1;
            o0.x = acc[i][0] + bv[0]; o0.y = acc[i][1] + bv[1];
            o0.z = acc[i][2] + bv[2]; o0.w = acc[i][3] + bv[3];
            o1.x = acc[i][4] + bv[4]; o1.y = acc[i][5] + bv[5];
            o1.z = acc[i][6] + bv[6]; o1.w = acc[i][7] + bv[7];
            float4* p = reinterpret_cast<float4*>(&g_ht[gr * DD + n0 + tc * 8]);
            p[0] = o0;
            p[1] = o1;
        }
    }
}

// ---------------------------------------------------------------------------
// FUSED: CSR gather-aggregate + self-loop + LayerNorm + ReLU.
// One warp per destination row; accumulators live in registers.
//   out[d] = relu(LN( isq[d] * ( ht[d]*isq[d] + sum_s ht[s]*isq[s] ) ))
// which equals agg + ht/deg with the symmetric GCN norm.
// ---------------------------------------------------------------------------
__global__ __launch_bounds__(256) void k_agg_ln(const float* __restrict__ gamma,
                                                const float* __restrict__ beta,
                                                float* __restrict__ out, int to_out) {
    int row = blockIdx.x * 8 + (threadIdx.x >> 5);
    if (row >= NN) return;
    int lane = threadIdx.x & 31;

    float isq_r = g_isq[row];

    const float4* ph = reinterpret_cast<const float4*>(&g_ht[(size_t)row * DD]);
    float4 acc[4];
    #pragma unroll
    for (int j = 0; j < 4; j++) {
        float4 v = ph[lane + 32 * j];
        acc[j].x = v.x * isq_r; acc[j].y = v.y * isq_r;
        acc[j].z = v.z * isq_r; acc[j].w = v.w * isq_r;
    }

    int e  = g_row_off[row];
    int e1 = g_row_off[row + 1];
    // Unroll-2 over edges for MLP
    for (; e + 1 < e1; e += 2) {
        int s0 = g_csr_src[e];
        int s1 = g_csr_src[e + 1];
        float w0 = g_isq[s0];
        float w1 = g_isq[s1];
        const float4* p0 = reinterpret_cast<const float4*>(&g_ht[(size_t)s0 * DD]);
        const float4* p1 = reinterpret_cast<const float4*>(&g_ht[(size_t)s1 * DD]);
        #pragma unroll
        for (int j = 0; j < 4; j++) {
            float4 v0 = p0[lane + 32 * j];
            float4 v1 = p1[lane + 32 * j];
            acc[j].x += v0.x * w0 + v1.x * w1;
            acc[j].y += v0.y * w0 + v1.y * w1;
            acc[j].z += v0.z * w0 + v1.z * w1;
            acc[j].w += v0.w * w0 + v1.w * w1;
        }
    }
    if (e < e1) {
        int s0 = g_csr_src[e];
        float w0 = g_isq[s0];
        const float4* p0 = reinterpret_cast<const float4*>(&g_ht[(size_t)s0 * DD]);
        #pragma unroll
        for (int j = 0; j < 4; j++) {
            float4 v0 = p0[lane + 32 * j];
            acc[j].x += v0.x * w0;
            acc[j].y += v0.y * w0;
            acc[j].z += v0.z * w0;
            acc[j].w += v0.w * w0;
        }
    }

    // Final symmetric-norm scale + LN statistics
    float sum = 0.f, sq = 0.f;
    #pragma unroll
    for (int j = 0; j < 4; j++) {
        acc[j].x *= isq_r; acc[j].y *= isq_r;
        acc[j].z *= isq_r; acc[j].w *= isq_r;
        sum += acc[j].x + acc[j].y + acc[j].z + acc[j].w;
        sq  += acc[j].x * acc[j].x + acc[j].y * acc[j].y
             + acc[j].z * acc[j].z + acc[j].w * acc[j].w;
    }
    #pragma unroll
    for (int o = 16; o > 0; o >>= 1) {
        sum += __shfl_xor_sync(0xffffffffu, sum, o);
        sq  += __shfl_xor_sync(0xffffffffu, sq, o);
    }
    float mean = sum * (1.0f / DD);
    float var  = sq * (1.0f / DD) - mean * mean;
    float rstd = rsqrtf(var + LN_EPS);

    float* __restrict__ po = to_out ? out : (float*)g_h;
    #pragma unroll
    for (int j = 0; j < 4; j++) {
        int col = (lane + 32 * j) * 4;
        float4 a = acc[j];
        float4 r;
        r.x = fmaxf(gamma[col + 0] * (a.x - mean) * rstd + beta[col + 0], 0.f);
        r.y = fmaxf(gamma[col + 1] * (a.y - mean) * rstd + beta[col + 1], 0.f);
        r.z = fmaxf(gamma[col + 2] * (a.z - mean) * rstd + beta[col + 2], 0.f);
        r.w = fmaxf(gamma[col + 3] * (a.w - mean) * rstd + beta[col + 3], 0.f);
        reinterpret_cast<float4*>(&po[(size_t)row * DD])[lane + 32 * j] = r;
    }
}

// ---------------------------------------------------------------------------
extern "C" void kernel_launch(void* const* d_in, const int* in_sizes, int n_in,
                              void* d_out, int out_size) {
    const float* x      = (const float*)d_in[0];   // [NN, DD]
    const int*   edge   = (const int*)  d_in[1];   // [2, NE]
    const float* Ws     = (const float*)d_in[2];   // [NL, DD, DD]
    const float* bs     = (const float*)d_in[3];   // [NL, DD]
    const float* gammas = (const float*)d_in[4];   // [NL, DD]
    const float* betas  = (const float*)d_in[5];   // [NL, DD]
    float* out = (float*)d_out;

    const int* src = edge;
    const int* dst = edge + NE;

    // Graph preprocessing (once; reused by all layers)
    k_deg_init<<<(NN + 255) / 256, 256>>>();
    k_deg_accum<<<(NE + 255) / 256, 256>>>(dst);
    k_isq<<<(NN + 255) / 256, 256>>>();
    k_scan<<<1, 1024>>>();
    k_fill<<<(NE + 255) / 256, 256>>>(src, dst);

    dim3 ggrid((NN + 127) / 128, DD / 128);
    for (int l = 0; l < NL; l++) {
        k_gemm<<<ggrid, 256>>>(x, l == 0 ? 1 : 0, Ws + l * DD * DD, bs + l * DD);
        k_agg_ln<<<(NN + 7) / 8, 256>>>(gammas + l * DD, betas + l * DD,
                                        out, l == NL - 1 ? 1 : 0);
    }
}

// round 3
// speedup vs baseline: 2.5003x; 1.8150x over previous
#include <cuda_runtime.h>
#include <cuda_bf16.h>
#include <cstdint>

#define NN 50000
#define NE 800000
#define DD 512
#define NL 3
#define LN_EPS 1e-5f

// Scratch (device globals — no allocation allowed)
__device__ float g_ht[NN * DD];    // linear output per layer
__device__ float g_h[NN * DD];     // hidden state between layers
__device__ float g_deg[NN];
__device__ float g_isq[NN];
__device__ int   g_row_off[NN + 1];
__device__ int   g_cursor[NN];
__device__ int   g_csr_src[NE];

// ---------------------------------------------------------------------------
// Degree: deg = 1 + incoming-edge count
// ---------------------------------------------------------------------------
__global__ void k_deg_init() {
    int i = blockIdx.x * blockDim.x + threadIdx.x;
    if (i < NN) g_deg[i] = 1.0f;
}

__global__ void k_deg_accum(const int* __restrict__ dst) {
    int e = blockIdx.x * blockDim.x + threadIdx.x;
    if (e < NE) atomicAdd(&g_deg[dst[e]], 1.0f);
}

__global__ void k_isq() {
    int i = blockIdx.x * blockDim.x + threadIdx.x;
    if (i < NN) g_isq[i] = rsqrtf(g_deg[i]);
}

// ---------------------------------------------------------------------------
// Coalesced block-wide prefix scan of in-degrees -> CSR offsets.
// 1024 threads, pass-based: each pass scans 1024 contiguous elements.
// ---------------------------------------------------------------------------
__global__ void k_scan() {
    __shared__ int wsum[32];
    __shared__ int carry;
    int t = threadIdx.x, w = t >> 5, l = t & 31;
    if (t == 0) carry = 0;
    __syncthreads();
    const int NPASS = (NN + 1023) / 1024;
    for (int p = 0; p < NPASS; p++) {
        int idx = p * 1024 + t;
        int c = (idx < NN) ? (int)(g_deg[idx] - 1.0f) : 0;
        int incl = c;
        #pragma unroll
        for (int o = 1; o < 32; o <<= 1) {
            int v = __shfl_up_sync(0xffffffffu, incl, o);
            if (l >= o) incl += v;
        }
        if (l == 31) wsum[w] = incl;
        __syncthreads();
        if (w == 0) {
            int v = wsum[l];
            #pragma unroll
            for (int o = 1; o < 32; o <<= 1) {
                int u = __shfl_up_sync(0xffffffffu, v, o);
                if (l >= o) v += u;
            }
            wsum[l] = v;
        }
        __syncthreads();
        int base = carry + (w ? wsum[w - 1] : 0);
        int excl = base + incl - c;
        if (idx < NN) { g_row_off[idx] = excl; g_cursor[idx] = excl; }
        __syncthreads();
        if (t == 0) carry += wsum[31];
        __syncthreads();
    }
    if (t == 0) g_row_off[NN] = carry;
}

__global__ void k_fill(const int* __restrict__ src, const int* __restrict__ dst) {
    int e = blockIdx.x * blockDim.x + threadIdx.x;
    if (e < NE) {
        int p = atomicAdd(&g_cursor[dst[e]], 1);
        g_csr_src[p] = src[e];
    }
}

// ---------------------------------------------------------------------------
// Tensor-core GEMM: g_ht = A @ W + bias (fp32 in/out, bf16-split HMMA inside)
// BM=128, BN=128, BK=32; 256 threads = 8 warps (4m x 2n), warp tile 32x64.
// Split: A = Ah+Al, B = Bh+Bl (bf16); acc += Ah*Bh + Al*Bh + Ah*Bl.
// ---------------------------------------------------------------------------
__device__ __forceinline__ uint32_t swzA(uint32_t a) { return a ^ ((a >> 3) & 0x30); }
__device__ __forceinline__ uint32_t swzB(uint32_t a) { return a ^ ((a >> 4) & 0x70); }

__device__ __forceinline__ void bf16_split_pack(float x, float y,
                                                uint32_t& hi, uint32_t& lo) {
    __nv_bfloat162 h = __floats2bfloat162_rn(x, y);
    float rx = x - __bfloat162float(h.x);
    float ry = y - __bfloat162float(h.y);
    __nv_bfloat162 lw = __floats2bfloat162_rn(rx, ry);
    hi = *reinterpret_cast<uint32_t*>(&h);
    lo = *reinterpret_cast<uint32_t*>(&lw);
}

__device__ __forceinline__ void ldsm_x4(uint32_t* r, uint32_t addr) {
    asm volatile("ldmatrix.sync.aligned.m8n8.x4.shared.b16 {%0,%1,%2,%3}, [%4];"
                 : "=r"(r[0]), "=r"(r[1]), "=r"(r[2]), "=r"(r[3]) : "r"(addr));
}
__device__ __forceinline__ void ldsm_x4_t(uint32_t* r, uint32_t addr) {
    asm volatile("ldmatrix.sync.aligned.m8n8.x4.trans.shared.b16 {%0,%1,%2,%3}, [%4];"
                 : "=r"(r[0]), "=r"(r[1]), "=r"(r[2]), "=r"(r[3]) : "r"(addr));
}
__device__ __forceinline__ void mma16816(float* c, const uint32_t* a, const uint32_t* b) {
    asm volatile("mma.sync.aligned.m16n8k16.row.col.f32.bf16.bf16.f32 "
                 "{%0,%1,%2,%3}, {%4,%5,%6,%7}, {%8,%9}, {%0,%1,%2,%3};"
                 : "+f"(c[0]), "+f"(c[1]), "+f"(c[2]), "+f"(c[3])
                 : "r"(a[0]), "r"(a[1]), "r"(a[2]), "r"(a[3]), "r"(b[0]), "r"(b[1]));
}

__global__ __launch_bounds__(256, 1) void k_gemm(const float* __restrict__ x, int use_x,
                                                 const float* __restrict__ W,
                                                 const float* __restrict__ bias) {
    const float* __restrict__ A = use_x ? x : (const float*)g_h;

    __shared__ __align__(128) unsigned char sm[32768];
    uint32_t sbase;
    {
        void* p = sm;
        sbase = (uint32_t)__cvta_generic_to_shared(p);
    }
    const uint32_t sA_hi = sbase;
    const uint32_t sA_lo = sbase + 8192;
    const uint32_t sB_hi = sbase + 16384;
    const uint32_t sB_lo = sbase + 24576;

    int t = threadIdx.x;
    int lane = t & 31;
    int warp = t >> 5;
    int m0 = blockIdx.x * 128;
    int n0 = blockIdx.y * 128;
    int wm = (warp & 3) * 32;   // warp m-offset
    int wn = (warp >> 2) * 64;  // warp n-offset

    float acc[2][8][4];
    #pragma unroll
    for (int i = 0; i < 2; i++)
        #pragma unroll
        for (int j = 0; j < 8; j++)
            #pragma unroll
            for (int q = 0; q < 4; q++) acc[i][j][q] = 0.f;

    // Load mappings
    int aRow = t >> 3;          // + 32*h  (rows 0..127)
    int aCol = (t & 7) * 4;     // fp32 col within BK=32
    int bRow = t >> 5;          // + 8*h   (rows 0..31)
    int bCol = (t & 31) * 4;    // fp32 col within BN=128

    float4 ra[4], rb[4];

    auto loadA = [&](int kb) {
        #pragma unroll
        for (int h = 0; h < 4; h++) {
            int gr = m0 + aRow + 32 * h;
            ra[h] = (gr < NN)
                ? *reinterpret_cast<const float4*>(&A[(size_t)gr * DD + kb * 32 + aCol])
                : make_float4(0.f, 0.f, 0.f, 0.f);
        }
    };
    auto loadB = [&](int kb) {
        #pragma unroll
        for (int h = 0; h < 4; h++) {
            int r = kb * 32 + bRow + 8 * h;
            rb[h] = *reinterpret_cast<const float4*>(&W[(size_t)r * DD + n0 + bCol]);
        }
    };

    loadA(0); loadB(0);

    const int NIT = DD / 32;  // 16
    for (int kb = 0; kb < NIT; kb++) {
        // store prefetched tiles to smem as bf16 hi/lo
        #pragma unroll
        for (int h = 0; h < 4; h++) {
            uint32_t hi0, lo0, hi1, lo1;
            bf16_split_pack(ra[h].x, ra[h].y, hi0, lo0);
            bf16_split_pack(ra[h].z, ra[h].w, hi1, lo1);
            uint32_t ad = (uint32_t)(aRow + 32 * h) * 64 + aCol * 2;
            *(uint32_t*)__cvta_shared_to_generic(sA_hi + swzA(ad))     = hi0;
            *(uint32_t*)__cvta_shared_to_generic(sA_hi + swzA(ad + 4)) = hi1;
            *(uint32_t*)__cvta_shared_to_generic(sA_lo + swzA(ad))     = lo0;
            *(uint32_t*)__cvta_shared_to_generic(sA_lo + swzA(ad + 4)) = lo1;
        }
        #pragma unroll
        for (int h = 0; h < 4; h++) {
            uint32_t hi0, lo0, hi1, lo1;
            bf16_split_pack(rb[h].x, rb[h].y, hi0, lo0);
            bf16_split_pack(rb[h].z, rb[h].w, hi1, lo1);
            uint32_t ad = (uint32_t)(bRow + 8 * h) * 256 + bCol * 2;
            *(uint32_t*)__cvta_shared_to_generic(sB_hi + swzB(ad))     = hi0;
            *(uint32_t*)__cvta_shared_to_generic(sB_hi + swzB(ad + 4)) = hi1;
            *(uint32_t*)__cvta_shared_to_generic(sB_lo + swzB(ad))     = lo0;
            *(uint32_t*)__cvta_shared_to_generic(sB_lo + swzB(ad + 4)) = lo1;
        }
        __syncthreads();

        if (kb + 1 < NIT) { loadA(kb + 1); loadB(kb + 1); }

        #pragma unroll
        for (int ks = 0; ks < 2; ks++) {
            int k = ks * 16;
            uint32_t ah[2][4], al[2][4];
            #pragma unroll
            for (int mi = 0; mi < 2; mi++) {
                uint32_t ad = (uint32_t)(wm + mi * 16 + (lane & 15)) * 64
                            + (uint32_t)(k + 8 * (lane >> 4)) * 2;
                ldsm_x4(ah[mi], sA_hi + swzA(ad));
                ldsm_x4(al[mi], sA_lo + swzA(ad));
            }
            #pragma unroll
            for (int nj = 0; nj < 4; nj++) {
                uint32_t bh[4], bl[4];
                uint32_t bd = (uint32_t)(k + (lane & 15)) * 256
                            + (uint32_t)(wn + nj * 16 + 8 * (lane >> 4)) * 2;
                ldsm_x4_t(bh, sB_hi + swzB(bd));
                ldsm_x4_t(bl, sB_lo + swzB(bd));
                #pragma unroll
                for (int mi = 0; mi < 2; mi++) {
                    #pragma unroll
                    for (int hf = 0; hf < 2; hf++) {
                        float* c = acc[mi][nj * 2 + hf];
                        mma16816(c, ah[mi], bh + 2 * hf);
                        mma16816(c, al[mi], bh + 2 * hf);
                        mma16816(c, ah[mi], bl + 2 * hf);
                    }
                }
            }
        }
        __syncthreads();
    }

    // Epilogue: add bias, store fp32
    #pragma unroll
    for (int mi = 0; mi < 2; mi++) {
        #pragma unroll
        for (int nf = 0; nf < 8; nf++) {
            int row = m0 + wm + mi * 16 + (lane >> 2);
            int col = n0 + wn + nf * 8 + (lane & 3) * 2;
            float b0 = bias[col], b1 = bias[col + 1];
            float* c = acc[mi][nf];
            if (row < NN) {
                float2 v = make_float2(c[0] + b0, c[1] + b1);
                *reinterpret_cast<float2*>(&g_ht[(size_t)row * DD + col]) = v;
            }
            if (row + 8 < NN) {
                float2 v = make_float2(c[2] + b0, c[3] + b1);
                *reinterpret_cast<float2*>(&g_ht[(size_t)(row + 8) * DD + col]) = v;
            }
        }
    }
}

// ---------------------------------------------------------------------------
// FUSED: CSR gather-aggregate + self-loop + LayerNorm + ReLU.
// One warp per destination row; accumulators in registers.
// ---------------------------------------------------------------------------
__global__ __launch_bounds__(256) void k_agg_ln(const float* __restrict__ gamma,
                                                const float* __restrict__ beta,
                                                float* __restrict__ out, int to_out) {
    int row = blockIdx.x * 8 + (threadIdx.x >> 5);
    if (row >= NN) return;
    int lane = threadIdx.x & 31;

    float isq_r = g_isq[row];

    const float4* ph = reinterpret_cast<const float4*>(&g_ht[(size_t)row * DD]);
    float4 acc[4];
    #pragma unroll
    for (int j = 0; j < 4; j++) {
        float4 v = ph[lane + 32 * j];
        acc[j].x = v.x * isq_r; acc[j].y = v.y * isq_r;
        acc[j].z = v.z * isq_r; acc[j].w = v.w * isq_r;
    }

    int e  = g_row_off[row];
    int e1 = g_row_off[row + 1];
    for (; e + 1 < e1; e += 2) {
        int s0 = g_csr_src[e];
        int s1 = g_csr_src[e + 1];
        float w0 = g_isq[s0];
        float w1 = g_isq[s1];
        const float4* p0 = reinterpret_cast<const float4*>(&g_ht[(size_t)s0 * DD]);
        const float4* p1 = reinterpret_cast<const float4*>(&g_ht[(size_t)s1 * DD]);
        #pragma unroll
        for (int j = 0; j < 4; j++) {
            float4 v0 = p0[lane + 32 * j];
            float4 v1 = p1[lane + 32 * j];
            acc[j].x += v0.x * w0 + v1.x * w1;
            acc[j].y += v0.y * w0 + v1.y * w1;
            acc[j].z += v0.z * w0 + v1.z * w1;
            acc[j].w += v0.w * w0 + v1.w * w1;
        }
    }
    if (e < e1) {
        int s0 = g_csr_src[e];
        float w0 = g_isq[s0];
        const float4* p0 = reinterpret_cast<const float4*>(&g_ht[(size_t)s0 * DD]);
        #pragma unroll
        for (int j = 0; j < 4; j++) {
            float4 v0 = p0[lane + 32 * j];
            acc[j].x += v0.x * w0;
            acc[j].y += v0.y * w0;
            acc[j].z += v0.z * w0;
            acc[j].w += v0.w * w0;
        }
    }

    float sum = 0.f, sq = 0.f;
    #pragma unroll
    for (int j = 0; j < 4; j++) {
        acc[j].x *= isq_r; acc[j].y *= isq_r;
        acc[j].z *= isq_r; acc[j].w *= isq_r;
        sum += acc[j].x + acc[j].y + acc[j].z + acc[j].w;
        sq  += acc[j].x * acc[j].x + acc[j].y * acc[j].y
             + acc[j].z * acc[j].z + acc[j].w * acc[j].w;
    }
    #pragma unroll
    for (int o = 16; o > 0; o >>= 1) {
        sum += __shfl_xor_sync(0xffffffffu, sum, o);
        sq  += __shfl_xor_sync(0xffffffffu, sq, o);
    }
    float mean = sum * (1.0f / DD);
    float var  = sq * (1.0f / DD) - mean * mean;
    float rstd = rsqrtf(var + LN_EPS);

    float* __restrict__ po = to_out ? out : (float*)g_h;
    #pragma unroll
    for (int j = 0; j < 4; j++) {
        int col = (lane + 32 * j) * 4;
        float4 a = acc[j];
        float4 r;
        r.x = fmaxf(gamma[col + 0] * (a.x - mean) * rstd + beta[col + 0], 0.f);
        r.y = fmaxf(gamma[col + 1] * (a.y - mean) * rstd + beta[col + 1], 0.f);
        r.z = fmaxf(gamma[col + 2] * (a.z - mean) * rstd + beta[col + 2], 0.f);
        r.w = fmaxf(gamma[col + 3] * (a.w - mean) * rstd + beta[col + 3], 0.f);
        reinterpret_cast<float4*>(&po[(size_t)row * DD])[lane + 32 * j] = r;
    }
}

// ---------------------------------------------------------------------------
extern "C" void kernel_launch(void* const* d_in, const int* in_sizes, int n_in,
                              void* d_out, int out_size) {
    const float* x      = (const float*)d_in[0];   // [NN, DD]
    const int*   edge   = (const int*)  d_in[1];   // [2, NE]
    const float* Ws     = (const float*)d_in[2];   // [NL, DD, DD]
    const float* bs     = (const float*)d_in[3];   // [NL, DD]
    const float* gammas = (const float*)d_in[4];   // [NL, DD]
    const float* betas  = (const float*)d_in[5];   // [NL, DD]
    float* out = (float*)d_out;

    const int* src = edge;
    const int* dst = edge + NE;

    k_deg_init<<<(NN + 255) / 256, 256>>>();
    k_deg_accum<<<(NE + 255) / 256, 256>>>(dst);
    k_isq<<<(NN + 255) / 256, 256>>>();
    k_scan<<<1, 1024>>>();
    k_fill<<<(NE + 255) / 256, 256>>>(src, dst);

    dim3 ggrid((NN + 127) / 128, DD / 128);
    for (int l = 0; l < NL; l++) {
        k_gemm<<<ggrid, 256>>>(x, l == 0 ? 1 : 0, Ws + l * DD * DD, bs + l * DD);
        k_agg_ln<<<(NN + 7) / 8, 256>>>(gammas + l * DD, betas + l * DD,
                                        out, l == NL - 1 ? 1 : 0);
    }
}

// round 4
// speedup vs baseline: 2.9806x; 1.1921x over previous
#include <cuda_runtime.h>
#include <cuda_bf16.h>
#include <cstdint>

#define NN 50000
#define NE 800000
#define DD 512
#define NL 3
#define LN_EPS 1e-5f
#define SCAN_NB 49   // ceil(NN/1024)

// Scratch (device globals — no allocation allowed)
__device__ float g_ht[NN * DD];                  // GEMM output (fp32)
__device__ __nv_bfloat16 g_a_hi[NN * DD];        // layer input, bf16 high part
__device__ __nv_bfloat16 g_a_lo[NN * DD];        // layer input, bf16 low part
__device__ __nv_bfloat16 g_W_hi[NL * DD * DD];
__device__ __nv_bfloat16 g_W_lo[NL * DD * DD];
__device__ float g_deg[NN];
__device__ float g_isq[NN];
__device__ int   g_row_off[NN + 1];
__device__ int   g_cursor[NN];
__device__ int   g_csr_src[NE];
__device__ int   g_blksum[SCAN_NB];
__device__ int   g_blkoff[SCAN_NB];

// ---------------------------------------------------------------------------
__device__ __forceinline__ void bf16_split_pack(float x, float y,
                                                uint32_t& hi, uint32_t& lo) {
    __nv_bfloat162 h = __floats2bfloat162_rn(x, y);
    float rx = x - __bfloat162float(h.x);
    float ry = y - __bfloat162float(h.y);
    __nv_bfloat162 lw = __floats2bfloat162_rn(rx, ry);
    hi = *reinterpret_cast<uint32_t*>(&h);
    lo = *reinterpret_cast<uint32_t*>(&lw);
}

// Pre-conversion kernels: run once per launch
__global__ void k_convW(const float* __restrict__ Ws) {
    size_t i = (size_t)blockIdx.x * 256 + threadIdx.x;   // pair index
    float2 v = reinterpret_cast<const float2*>(Ws)[i];
    uint32_t hi, lo;
    bf16_split_pack(v.x, v.y, hi, lo);
    reinterpret_cast<uint32_t*>(g_W_hi)[i] = hi;
    reinterpret_cast<uint32_t*>(g_W_lo)[i] = lo;
}

__global__ void k_convX(const float* __restrict__ x) {
    size_t i = (size_t)blockIdx.x * 256 + threadIdx.x;   // pair index
    float2 v = reinterpret_cast<const float2*>(x)[i];
    uint32_t hi, lo;
    bf16_split_pack(v.x, v.y, hi, lo);
    reinterpret_cast<uint32_t*>(g_a_hi)[i] = hi;
    reinterpret_cast<uint32_t*>(g_a_lo)[i] = lo;
}

// ---------------------------------------------------------------------------
// Degree: deg = 1 + incoming-edge count
// ---------------------------------------------------------------------------
__global__ void k_deg_init() {
    int i = blockIdx.x * blockDim.x + threadIdx.x;
    if (i < NN) g_deg[i] = 1.0f;
}
__global__ void k_deg_accum(const int* __restrict__ dst) {
    int e = blockIdx.x * blockDim.x + threadIdx.x;
    if (e < NE) atomicAdd(&g_deg[dst[e]], 1.0f);
}
__global__ void k_isq() {
    int i = blockIdx.x * blockDim.x + threadIdx.x;
    if (i < NN) g_isq[i] = rsqrtf(g_deg[i]);
}

// ---------------------------------------------------------------------------
// Multi-block scan: per-block scan -> block-offset scan -> add offsets
// ---------------------------------------------------------------------------
__global__ void k_scan1() {
    __shared__ int wsum[32];
    int b = blockIdx.x, t = threadIdx.x, w = t >> 5, l = t & 31;
    int idx = b * 1024 + t;
    int c = (idx < NN) ? (int)(g_deg[idx] - 1.0f) : 0;
    int incl = c;
    #pragma unroll
    for (int o = 1; o < 32; o <<= 1) {
        int v = __shfl_up_sync(0xffffffffu, incl, o);
        if (l >= o) incl += v;
    }
    if (l == 31) wsum[w] = incl;
    __syncthreads();
    if (w == 0) {
        int v = wsum[l];
        #pragma unroll
        for (int o = 1; o < 32; o <<= 1) {
            int u = __shfl_up_sync(0xffffffffu, v, o);
            if (l >= o) v += u;
        }
        wsum[l] = v;
    }
    __syncthreads();
    int excl = (w ? wsum[w - 1] : 0) + incl - c;
    if (idx < NN) g_row_off[idx] = excl;
    if (t == 1023) g_blksum[b] = wsum[31];
}

__global__ void k_scan2() {
    int t = threadIdx.x, l = t & 31, w = t >> 5;
    __shared__ int ws[2];
    int v = (t < SCAN_NB) ? g_blksum[t] : 0;
    int incl = v;
    #pragma unroll
    for (int o = 1; o < 32; o <<= 1) {
        int u = __shfl_up_sync(0xffffffffu, incl, o);
        if (l >= o) incl += u;
    }
    if (l == 31) ws[w] = incl;
    __syncthreads();
    int inclusive = incl + (w == 1 ? ws[0] : 0);
    if (t < SCAN_NB) g_blkoff[t] = inclusive - v;
    if (t == SCAN_NB - 1) g_row_off[NN] = inclusive;
}

__global__ void k_scan3() {
    int b = blockIdx.x;
    int idx = b * 1024 + threadIdx.x;
    if (idx < NN) {
        int v = g_row_off[idx] + g_blkoff[b];
        g_row_off[idx] = v;
        g_cursor[idx]  = v;
    }
}

__global__ void k_fill(const int* __restrict__ src, const int* __restrict__ dst) {
    int e = blockIdx.x * blockDim.x + threadIdx.x;
    if (e < NE) {
        int p = atomicAdd(&g_cursor[dst[e]], 1);
        g_csr_src[p] = src[e];
    }
}

// ---------------------------------------------------------------------------
// Tensor-core GEMM with pre-split bf16 operands + cp.async double buffering.
// g_ht = A @ W_l + bias;  A = (g_a_hi,g_a_lo), W = (g_W_hi,g_W_lo)
// BM=128, BN=128, BK=32; 256 threads = 8 warps (4m x 2n), warp tile 32x64.
// acc += Ah*Bh + Al*Bh + Ah*Bl.
// ---------------------------------------------------------------------------
__device__ __forceinline__ uint32_t swzA(uint32_t a) { return a ^ ((a >> 3) & 0x30); }
__device__ __forceinline__ uint32_t swzB(uint32_t a) { return a ^ ((a >> 4) & 0x70); }

__device__ __forceinline__ void cpa16(uint32_t s, const void* g, int sz) {
    asm volatile("cp.async.cg.shared.global [%0], [%1], 16, %2;"
                 :: "r"(s), "l"(g), "r"(sz));
}
__device__ __forceinline__ void ldsm_x4(uint32_t* r, uint32_t addr) {
    asm volatile("ldmatrix.sync.aligned.m8n8.x4.shared.b16 {%0,%1,%2,%3}, [%4];"
                 : "=r"(r[0]), "=r"(r[1]), "=r"(r[2]), "=r"(r[3]) : "r"(addr));
}
__device__ __forceinline__ void ldsm_x4_t(uint32_t* r, uint32_t addr) {
    asm volatile("ldmatrix.sync.aligned.m8n8.x4.trans.shared.b16 {%0,%1,%2,%3}, [%4];"
                 : "=r"(r[0]), "=r"(r[1]), "=r"(r[2]), "=r"(r[3]) : "r"(addr));
}
__device__ __forceinline__ void mma16816(float* c, const uint32_t* a, const uint32_t* b) {
    asm volatile("mma.sync.aligned.m16n8k16.row.col.f32.bf16.bf16.f32 "
                 "{%0,%1,%2,%3}, {%4,%5,%6,%7}, {%8,%9}, {%0,%1,%2,%3};"
                 : "+f"(c[0]), "+f"(c[1]), "+f"(c[2]), "+f"(c[3])
                 : "r"(a[0]), "r"(a[1]), "r"(a[2]), "r"(a[3]), "r"(b[0]), "r"(b[1]));
}

// per-stage smem: A_hi 8K | A_lo 8K | B_hi 8K | B_lo 8K = 32 KB; 2 stages = 64 KB
#define STG_BYTES 32768

__global__ __launch_bounds__(256, 2) void k_gemm(int l, const float* __restrict__ bias) {
    extern __shared__ __align__(128) unsigned char sm[];
    uint32_t sbase = (uint32_t)__cvta_generic_to_shared(sm);

    const __nv_bfloat16* __restrict__ Ahi = g_a_hi;
    const __nv_bfloat16* __restrict__ Alo = g_a_lo;
    const __nv_bfloat16* __restrict__ Whi = g_W_hi + (size_t)l * DD * DD;
    const __nv_bfloat16* __restrict__ Wlo = g_W_lo + (size_t)l * DD * DD;

    int t = threadIdx.x;
    int lane = t & 31;
    int warp = t >> 5;
    int m0 = blockIdx.x * 128;
    int n0 = blockIdx.y * 128;
    int wm = (warp & 3) * 32;
    int wn = (warp >> 2) * 64;

    float acc[2][8][4];
    #pragma unroll
    for (int i = 0; i < 2; i++)
        #pragma unroll
        for (int j = 0; j < 8; j++)
            #pragma unroll
            for (int q = 0; q < 4; q++) acc[i][j][q] = 0.f;

    // cp.async load mappings
    int aRow = t >> 2;          // 0..63, +64*h
    int aU   = (t & 3);         // 16B unit within 64B row
    int bRow = t >> 3;          // 0..31
    int bU   = (t & 7);         // pair of 16B units within 256B row

    auto issue = [&](int kb) {
        int stg = kb & 1;
        uint32_t so = sbase + stg * STG_BYTES;
        #pragma unroll
        for (int h = 0; h < 2; h++) {
            int r = aRow + 64 * h;
            int gr = m0 + r;
            int sz = (gr < NN) ? 16 : 0;
            size_t gidx = (size_t)(gr < NN ? gr : 0) * DD + kb * 32 + aU * 8;
            uint32_t ad = swzA((uint32_t)r * 64 + aU * 16);
            cpa16(so + ad, &Ahi[gidx], sz);
            cpa16(so + 8192 + ad, &Alo[gidx], sz);
        }
        #pragma unroll
        for (int u = 0; u < 2; u++) {
            size_t gidx = (size_t)(kb * 32 + bRow) * DD + n0 + bU * 16 + u * 8;
            uint32_t bd = swzB((uint32_t)bRow * 256 + bU * 32 + u * 16);
            cpa16(so + 16384 + bd, &Whi[gidx], 16);
            cpa16(so + 24576 + bd, &Wlo[gidx], 16);
        }
    };

    const int NIT = DD / 32;  // 16
    issue(0);
    asm volatile("cp.async.commit_group;");

    for (int kb = 0; kb < NIT; kb++) {
        if (kb + 1 < NIT) issue(kb + 1);
        asm volatile("cp.async.commit_group;");
        asm volatile("cp.async.wait_group 1;");
        __syncthreads();

        int stg = kb & 1;
        uint32_t so = sbase + stg * STG_BYTES;
        uint32_t sA_hi = so, sA_lo = so + 8192, sB_hi = so + 16384, sB_lo = so + 24576;

        #pragma unroll
        for (int ks = 0; ks < 2; ks++) {
            int k = ks * 16;
            uint32_t ah[2][4], al[2][4];
            #pragma unroll
            for (int mi = 0; mi < 2; mi++) {
                uint32_t ad = (uint32_t)(wm + mi * 16 + (lane & 15)) * 64
                            + (uint32_t)(k + 8 * (lane >> 4)) * 2;
                ldsm_x4(ah[mi], sA_hi + swzA(ad));
                ldsm_x4(al[mi], sA_lo + swzA(ad));
            }
            #pragma unroll
            for (int nj = 0; nj < 4; nj++) {
                uint32_t bh[4], bl[4];
                uint32_t bd = (uint32_t)(k + (lane & 15)) * 256
                            + (uint32_t)(wn + nj * 16 + 8 * (lane >> 4)) * 2;
                ldsm_x4_t(bh, sB_hi + swzB(bd));
                ldsm_x4_t(bl, sB_lo + swzB(bd));
                #pragma unroll
                for (int mi = 0; mi < 2; mi++) {
                    #pragma unroll
                    for (int hf = 0; hf < 2; hf++) {
                        float* c = acc[mi][nj * 2 + hf];
                        mma16816(c, ah[mi], bh + 2 * hf);
                        mma16816(c, al[mi], bh + 2 * hf);
                        mma16816(c, ah[mi], bl + 2 * hf);
                    }
                }
            }
        }
        __syncthreads();
    }

    // Epilogue: add bias, store fp32
    #pragma unroll
    for (int mi = 0; mi < 2; mi++) {
        #pragma unroll
        for (int nf = 0; nf < 8; nf++) {
            int row = m0 + wm + mi * 16 + (lane >> 2);
            int col = n0 + wn + nf * 8 + (lane & 3) * 2;
            float b0 = bias[col], b1 = bias[col + 1];
            float* c = acc[mi][nf];
            if (row < NN) {
                float2 v = make_float2(c[0] + b0, c[1] + b1);
                *reinterpret_cast<float2*>(&g_ht[(size_t)row * DD + col]) = v;
            }
            if (row + 8 < NN) {
                float2 v = make_float2(c[2] + b0, c[3] + b1);
                *reinterpret_cast<float2*>(&g_ht[(size_t)(row + 8) * DD + col]) = v;
            }
        }
    }
}

// ---------------------------------------------------------------------------
// FUSED: CSR gather-aggregate + self-loop + LayerNorm + ReLU.
// Writes next-layer bf16 hi/lo inputs (intermediate) or fp32 out (final).
// ---------------------------------------------------------------------------
__global__ __launch_bounds__(256) void k_agg_ln(const float* __restrict__ gamma,
                                                const float* __restrict__ beta,
                                                float* __restrict__ out, int to_out) {
    int row = blockIdx.x * 8 + (threadIdx.x >> 5);
    if (row >= NN) return;
    int lane = threadIdx.x & 31;

    float isq_r = g_isq[row];

    const float4* ph = reinterpret_cast<const float4*>(&g_ht[(size_t)row * DD]);
    float4 acc[4];
    #pragma unroll
    for (int j = 0; j < 4; j++) {
        float4 v = ph[lane + 32 * j];
        acc[j].x = v.x * isq_r; acc[j].y = v.y * isq_r;
        acc[j].z = v.z * isq_r; acc[j].w = v.w * isq_r;
    }

    int e  = g_row_off[row];
    int e1 = g_row_off[row + 1];
    for (; e + 1 < e1; e += 2) {
        int s0 = g_csr_src[e];
        int s1 = g_csr_src[e + 1];
        float w0 = g_isq[s0];
        float w1 = g_isq[s1];
        const float4* p0 = reinterpret_cast<const float4*>(&g_ht[(size_t)s0 * DD]);
        const float4* p1 = reinterpret_cast<const float4*>(&g_ht[(size_t)s1 * DD]);
        #pragma unroll
        for (int j = 0; j < 4; j++) {
            float4 v0 = p0[lane + 32 * j];
            float4 v1 = p1[lane + 32 * j];
            acc[j].x += v0.x * w0 + v1.x * w1;
            acc[j].y += v0.y * w0 + v1.y * w1;
            acc[j].z += v0.z * w0 + v1.z * w1;
            acc[j].w += v0.w * w0 + v1.w * w1;
        }
    }
    if (e < e1) {
        int s0 = g_csr_src[e];
        float w0 = g_isq[s0];
        const float4* p0 = reinterpret_cast<const float4*>(&g_ht[(size_t)s0 * DD]);
        #pragma unroll
        for (int j = 0; j < 4; j++) {
            float4 v0 = p0[lane + 32 * j];
            acc[j].x += v0.x * w0;
            acc[j].y += v0.y * w0;
            acc[j].z += v0.z * w0;
            acc[j].w += v0.w * w0;
        }
    }

    float sum = 0.f, sq = 0.f;
    #pragma unroll
    for (int j = 0; j < 4; j++) {
        acc[j].x *= isq_r; acc[j].y *= isq_r;
        acc[j].z *= isq_r; acc[j].w *= isq_r;
        sum += acc[j].x + acc[j].y + acc[j].z + acc[j].w;
        sq  += acc[j].x * acc[j].x + acc[j].y * acc[j].y
             + acc[j].z * acc[j].z + acc[j].w * acc[j].w;
    }
    #pragma unroll
    for (int o = 16; o > 0; o >>= 1) {
        sum += __shfl_xor_sync(0xffffffffu, sum, o);
        sq  += __shfl_xor_sync(0xffffffffu, sq, o);
    }
    float mean = sum * (1.0f / DD);
    float var  = sq * (1.0f / DD) - mean * mean;
    float rstd = rsqrtf(var + LN_EPS);

    #pragma unroll
    for (int j = 0; j < 4; j++) {
        int col = (lane + 32 * j) * 4;
        float4 a = acc[j];
        float4 r;
        r.x = fmaxf(gamma[col + 0] * (a.x - mean) * rstd + beta[col + 0], 0.f);
        r.y = fmaxf(gamma[col + 1] * (a.y - mean) * rstd + beta[col + 1], 0.f);
        r.z = fmaxf(gamma[col + 2] * (a.z - mean) * rstd + beta[col + 2], 0.f);
        r.w = fmaxf(gamma[col + 3] * (a.w - mean) * rstd + beta[col + 3], 0.f);
        if (to_out) {
            reinterpret_cast<float4*>(&out[(size_t)row * DD])[lane + 32 * j] = r;
        } else {
            uint32_t hi0, lo0, hi1, lo1;
            bf16_split_pack(r.x, r.y, hi0, lo0);
            bf16_split_pack(r.z, r.w, hi1, lo1);
            size_t pidx = ((size_t)row * DD + col) >> 1;
            reinterpret_cast<uint32_t*>(g_a_hi)[pidx]     = hi0;
            reinterpret_cast<uint32_t*>(g_a_hi)[pidx + 1] = hi1;
            reinterpret_cast<uint32_t*>(g_a_lo)[pidx]     = lo0;
            reinterpret_cast<uint32_t*>(g_a_lo)[pidx + 1] = lo1;
        }
    }
}

// ---------------------------------------------------------------------------
extern "C" void kernel_launch(void* const* d_in, const int* in_sizes, int n_in,
                              void* d_out, int out_size) {
    const float* x      = (const float*)d_in[0];   // [NN, DD]
    const int*   edge   = (const int*)  d_in[1];   // [2, NE]
    const float* Ws     = (const float*)d_in[2];   // [NL, DD, DD]
    const float* bs     = (const float*)d_in[3];   // [NL, DD]
    const float* gammas = (const float*)d_in[4];   // [NL, DD]
    const float* betas  = (const float*)d_in[5];   // [NL, DD]
    float* out = (float*)d_out;

    const int* src = edge;
    const int* dst = edge + NE;

    cudaFuncSetAttribute(k_gemm, cudaFuncAttributeMaxDynamicSharedMemorySize,
                         2 * STG_BYTES);

    // One-time conversions + graph preprocessing
    k_convW<<<NL * DD * DD / 2 / 256, 256>>>(Ws);
    k_convX<<<NN * DD / 2 / 256, 256>>>(x);
    k_deg_init<<<(NN + 255) / 256, 256>>>();
    k_deg_accum<<<(NE + 255) / 256, 256>>>(dst);
    k_isq<<<(NN + 255) / 256, 256>>>();
    k_scan1<<<SCAN_NB, 1024>>>();
    k_scan2<<<1, 64>>>();
    k_scan3<<<SCAN_NB, 1024>>>();
    k_fill<<<(NE + 255) / 256, 256>>>(src, dst);

    dim3 ggrid((NN + 127) / 128, DD / 128);
    for (int l = 0; l < NL; l++) {
        k_gemm<<<ggrid, 256, 2 * STG_BYTES>>>(l, bs + l * DD);
        k_agg_ln<<<(NN + 7) / 8, 256>>>(gammas + l * DD, betas + l * DD,
                                        out, l == NL - 1 ? 1 : 0);
    }
}

// round 6
// speedup vs baseline: 2.9921x; 1.0038x over previous
#include <cuda_runtime.h>
#include <cuda_bf16.h>
#include <cstdint>

#define NN 50000
#define NE 800000
#define DD 512
#define NL 3
#define LN_EPS 1e-5f
#define SCAN_NB 49   // ceil(NN/1024)

// per-stage smem: A_hi 8K | A_lo 8K | B_hi 8K | B_lo 8K = 32 KB; 3 stages
#define STG_BYTES 32768
#define NSTAGE 3
#define SMEM_TOT (NSTAGE * STG_BYTES)

// Scratch (device globals — no allocation allowed)
__device__ float g_ht[NN * DD];                  // GEMM output (fp32)
__device__ __nv_bfloat16 g_a_hi[NN * DD];        // layer input, bf16 high part
__device__ __nv_bfloat16 g_a_lo[NN * DD];        // layer input, bf16 low part
__device__ __nv_bfloat16 g_W_hi[NL * DD * DD];
__device__ __nv_bfloat16 g_W_lo[NL * DD * DD];
__device__ float g_deg[NN];
__device__ float g_isq[NN];
__device__ int   g_row_off[NN + 1];
__device__ int   g_cursor[NN];
__device__ int   g_csr_src[NE];
__device__ int   g_blksum[SCAN_NB];
__device__ int   g_blkoff[SCAN_NB];

// ---------------------------------------------------------------------------
__device__ __forceinline__ void bf16_split_pack(float x, float y,
                                                uint32_t& hi, uint32_t& lo) {
    __nv_bfloat162 h = __floats2bfloat162_rn(x, y);
    float rx = x - __bfloat162float(h.x);
    float ry = y - __bfloat162float(h.y);
    __nv_bfloat162 lw = __floats2bfloat162_rn(rx, ry);
    hi = *reinterpret_cast<uint32_t*>(&h);
    lo = *reinterpret_cast<uint32_t*>(&lw);
}

__global__ void k_convW(const float* __restrict__ Ws) {
    size_t i = (size_t)blockIdx.x * 256 + threadIdx.x;   // pair index
    float2 v = reinterpret_cast<const float2*>(Ws)[i];
    uint32_t hi, lo;
    bf16_split_pack(v.x, v.y, hi, lo);
    reinterpret_cast<uint32_t*>(g_W_hi)[i] = hi;
    reinterpret_cast<uint32_t*>(g_W_lo)[i] = lo;
}

__global__ void k_convX(const float* __restrict__ x) {
    size_t i = (size_t)blockIdx.x * 256 + threadIdx.x;   // pair index
    float2 v = reinterpret_cast<const float2*>(x)[i];
    uint32_t hi, lo;
    bf16_split_pack(v.x, v.y, hi, lo);
    reinterpret_cast<uint32_t*>(g_a_hi)[i] = hi;
    reinterpret_cast<uint32_t*>(g_a_lo)[i] = lo;
}

// ---------------------------------------------------------------------------
// Degree / CSR preprocessing
// ---------------------------------------------------------------------------
__global__ void k_deg_init() {
    int i = blockIdx.x * blockDim.x + threadIdx.x;
    if (i < NN) g_deg[i] = 1.0f;
}
__global__ void k_deg_accum(const int* __restrict__ dst) {
    int e = blockIdx.x * blockDim.x + threadIdx.x;
    if (e < NE) atomicAdd(&g_deg[dst[e]], 1.0f);
}
__global__ void k_isq() {
    int i = blockIdx.x * blockDim.x + threadIdx.x;
    if (i < NN) g_isq[i] = rsqrtf(g_deg[i]);
}

__global__ void k_scan1() {
    __shared__ int wsum[32];
    int b = blockIdx.x, t = threadIdx.x, w = t >> 5, l = t & 31;
    int idx = b * 1024 + t;
    int c = (idx < NN) ? (int)(g_deg[idx] - 1.0f) : 0;
    int incl = c;
    #pragma unroll
    for (int o = 1; o < 32; o <<= 1) {
        int v = __shfl_up_sync(0xffffffffu, incl, o);
        if (l >= o) incl += v;
    }
    if (l == 31) wsum[w] = incl;
    __syncthreads();
    if (w == 0) {
        int v = wsum[l];
        #pragma unroll
        for (int o = 1; o < 32; o <<= 1) {
            int u = __shfl_up_sync(0xffffffffu, v, o);
            if (l >= o) v += u;
        }
        wsum[l] = v;
    }
    __syncthreads();
    int excl = (w ? wsum[w - 1] : 0) + incl - c;
    if (idx < NN) g_row_off[idx] = excl;
    if (t == 1023) g_blksum[b] = wsum[31];
}

__global__ void k_scan2() {
    int t = threadIdx.x, l = t & 31, w = t >> 5;
    __shared__ int ws[2];
    int v = (t < SCAN_NB) ? g_blksum[t] : 0;
    int incl = v;
    #pragma unroll
    for (int o = 1; o < 32; o <<= 1) {
        int u = __shfl_up_sync(0xffffffffu, incl, o);
        if (l >= o) incl += u;
    }
    if (l == 31) ws[w] = incl;
    __syncthreads();
    int inclusive = incl + (w == 1 ? ws[0] : 0);
    if (t < SCAN_NB) g_blkoff[t] = inclusive - v;
    if (t == SCAN_NB - 1) g_row_off[NN] = inclusive;
}

__global__ void k_scan3() {
    int b = blockIdx.x;
    int idx = b * 1024 + threadIdx.x;
    if (idx < NN) {
        int v = g_row_off[idx] + g_blkoff[b];
        g_row_off[idx] = v;
        g_cursor[idx]  = v;
    }
}

__global__ void k_fill(const int* __restrict__ src, const int* __restrict__ dst) {
    int e = blockIdx.x * blockDim.x + threadIdx.x;
    if (e < NE) {
        int p = atomicAdd(&g_cursor[dst[e]], 1);
        g_csr_src[p] = src[e];
    }
}

// ---------------------------------------------------------------------------
// Tensor-core GEMM with pre-split bf16 operands + 3-stage cp.async pipeline.
// g_ht = A @ W_l + bias; BM=128, BN=128, BK=32; 8 warps (4m x 2n), 32x64/warp.
// acc += Ah*Bh + Al*Bh + Ah*Bl  (term-major issue order).
// ---------------------------------------------------------------------------
__device__ __forceinline__ uint32_t swzA(uint32_t a) { return a ^ ((a >> 3) & 0x30); }
__device__ __forceinline__ uint32_t swzB(uint32_t a) { return a ^ ((a >> 4) & 0x70); }

__device__ __forceinline__ void cpa16(uint32_t s, const void* g, int sz) {
    asm volatile("cp.async.cg.shared.global [%0], [%1], 16, %2;"
                 :: "r"(s), "l"(g), "r"(sz));
}
__device__ __forceinline__ void ldsm_x4(uint32_t* r, uint32_t addr) {
    asm volatile("ldmatrix.sync.aligned.m8n8.x4.shared.b16 {%0,%1,%2,%3}, [%4];"
                 : "=r"(r[0]), "=r"(r[1]), "=r"(r[2]), "=r"(r[3]) : "r"(addr));
}
__device__ __forceinline__ void ldsm_x4_t(uint32_t* r, uint32_t addr) {
    asm volatile("ldmatrix.sync.aligned.m8n8.x4.trans.shared.b16 {%0,%1,%2,%3}, [%4];"
                 : "=r"(r[0]), "=r"(r[1]), "=r"(r[2]), "=r"(r[3]) : "r"(addr));
}
__device__ __forceinline__ void mma16816(float* c, const uint32_t* a, const uint32_t* b) {
    asm volatile("mma.sync.aligned.m16n8k16.row.col.f32.bf16.bf16.f32 "
                 "{%0,%1,%2,%3}, {%4,%5,%6,%7}, {%8,%9}, {%0,%1,%2,%3};"
                 : "+f"(c[0]), "+f"(c[1]), "+f"(c[2]), "+f"(c[3])
                 : "r"(a[0]), "r"(a[1]), "r"(a[2]), "r"(a[3]), "r"(b[0]), "r"(b[1]));
}

__global__ __launch_bounds__(256, 2) void k_gemm(int l, const float* __restrict__ bias) {
    extern __shared__ __align__(128) unsigned char sm[];
    uint32_t sbase = (uint32_t)__cvta_generic_to_shared(sm);

    const __nv_bfloat16* __restrict__ Ahi = g_a_hi;
    const __nv_bfloat16* __restrict__ Alo = g_a_lo;
    const __nv_bfloat16* __restrict__ Whi = g_W_hi + (size_t)l * DD * DD;
    const __nv_bfloat16* __restrict__ Wlo = g_W_lo + (size_t)l * DD * DD;

    int t = threadIdx.x;
    int lane = t & 31;
    int warp = t >> 5;
    int m0 = blockIdx.x * 128;
    int n0 = blockIdx.y * 128;
    int wm = (warp & 3) * 32;
    int wn = (warp >> 2) * 64;

    float acc[2][8][4];
    #pragma unroll
    for (int i = 0; i < 2; i++)
        #pragma unroll
        for (int j = 0; j < 8; j++)
            #pragma unroll
            for (int q = 0; q < 4; q++) acc[i][j][q] = 0.f;

    // cp.async load mappings
    int aRow = t >> 2;          // 0..63, +64*h
    int aU   = (t & 3);         // 16B unit within 64B row
    int bRow = t >> 3;          // 0..31
    int bU   = (t & 7);         // pair of 16B units within 256B row

    auto issue = [&](int kb) {
        uint32_t so = sbase + (uint32_t)(kb % NSTAGE) * STG_BYTES;
        #pragma unroll
        for (int h = 0; h < 2; h++) {
            int r = aRow + 64 * h;
            int gr = m0 + r;
            int sz = (gr < NN) ? 16 : 0;
            size_t gidx = (size_t)(gr < NN ? gr : 0) * DD + kb * 32 + aU * 8;
            uint32_t ad = swzA((uint32_t)r * 64 + aU * 16);
            cpa16(so + ad, &Ahi[gidx], sz);
            cpa16(so + 8192 + ad, &Alo[gidx], sz);
        }
        #pragma unroll
        for (int u = 0; u < 2; u++) {
            size_t gidx = (size_t)(kb * 32 + bRow) * DD + n0 + bU * 16 + u * 8;
            uint32_t bd = swzB((uint32_t)bRow * 256 + bU * 32 + u * 16);
            cpa16(so + 16384 + bd, &Whi[gidx], 16);
            cpa16(so + 24576 + bd, &Wlo[gidx], 16);
        }
    };

    const int NIT = DD / 32;  // 16
    issue(0);
    asm volatile("cp.async.commit_group;");
    issue(1);
    asm volatile("cp.async.commit_group;");

    for (int kb = 0; kb < NIT; kb++) {
        if (kb + 2 < NIT) {
            issue(kb + 2);
            asm volatile("cp.async.commit_group;");
            asm volatile("cp.async.wait_group 2;");
        } else if (kb + 2 == NIT) {
            asm volatile("cp.async.wait_group 1;");
        } else {
            asm volatile("cp.async.wait_group 0;");
        }
        __syncthreads();

        uint32_t so = sbase + (uint32_t)(kb % NSTAGE) * STG_BYTES;
        uint32_t sA_hi = so, sA_lo = so + 8192, sB_hi = so + 16384, sB_lo = so + 24576;

        #pragma unroll
        for (int ks = 0; ks < 2; ks++) {
            int k = ks * 16;
            uint32_t ah[2][4], al[2][4];
            #pragma unroll
            for (int mi = 0; mi < 2; mi++) {
                uint32_t ad = (uint32_t)(wm + mi * 16 + (lane & 15)) * 64
                            + (uint32_t)(k + 8 * (lane >> 4)) * 2;
                ldsm_x4(ah[mi], sA_hi + swzA(ad));
                ldsm_x4(al[mi], sA_lo + swzA(ad));
            }
            #pragma unroll
            for (int nj = 0; nj < 4; nj++) {
                uint32_t bh[4], bl[4];
                uint32_t bd = (uint32_t)(k + (lane & 15)) * 256
                            + (uint32_t)(wn + nj * 16 + 8 * (lane >> 4)) * 2;
                ldsm_x4_t(bh, sB_hi + swzB(bd));
                ldsm_x4_t(bl, sB_lo + swzB(bd));
                // term-major: 4 independent accumulators between reuses
                #pragma unroll
                for (int mi = 0; mi < 2; mi++)
                    #pragma unroll
                    for (int hf = 0; hf < 2; hf++)
                        mma16816(acc[mi][nj * 2 + hf], ah[mi], bh + 2 * hf);
                #pragma unroll
                for (int mi = 0; mi < 2; mi++)
                    #pragma unroll
                    for (int hf = 0; hf < 2; hf++)
                        mma16816(acc[mi][nj * 2 + hf], al[mi], bh + 2 * hf);
                #pragma unroll
                for (int mi = 0; mi < 2; mi++)
                    #pragma unroll
                    for (int hf = 0; hf < 2; hf++)
                        mma16816(acc[mi][nj * 2 + hf], ah[mi], bl + 2 * hf);
            }
        }
        __syncthreads();
    }

    // Epilogue: add bias, store fp32
    #pragma unroll
    for (int mi = 0; mi < 2; mi++) {
        #pragma unroll
        for (int nf = 0; nf < 8; nf++) {
            int row = m0 + wm + mi * 16 + (lane >> 2);
            int col = n0 + wn + nf * 8 + (lane & 3) * 2;
            float b0 = bias[col], b1 = bias[col + 1];
            float* c = acc[mi][nf];
            if (row < NN) {
                float2 v = make_float2(c[0] + b0, c[1] + b1);
                *reinterpret_cast<float2*>(&g_ht[(size_t)row * DD + col]) = v;
            }
            if (row + 8 < NN) {
                float2 v = make_float2(c[2] + b0, c[3] + b1);
                *reinterpret_cast<float2*>(&g_ht[(size_t)(row + 8) * DD + col]) = v;
            }
        }
    }
}

// ---------------------------------------------------------------------------
// FUSED: CSR gather-aggregate + self-loop + LayerNorm + ReLU.
// ---------------------------------------------------------------------------
__global__ __launch_bounds__(256) void k_agg_ln(const float* __restrict__ gamma,
                                                const float* __restrict__ beta,
                                                float* __restrict__ out, int to_out) {
    int row = blockIdx.x * 8 + (threadIdx.x >> 5);
    if (row >= NN) return;
    int lane = threadIdx.x & 31;

    float isq_r = g_isq[row];

    const float4* ph = reinterpret_cast<const float4*>(&g_ht[(size_t)row * DD]);
    float4 acc[4];
    #pragma unroll
    for (int j = 0; j < 4; j++) {
        float4 v = ph[lane + 32 * j];
        acc[j].x = v.x * isq_r; acc[j].y = v.y * isq_r;
        acc[j].z = v.z * isq_r; acc[j].w = v.w * isq_r;
    }

    int e  = g_row_off[row];
    int e1 = g_row_off[row + 1];
    for (; e + 1 < e1; e += 2) {
        int s0 = g_csr_src[e];
        int s1 = g_csr_src[e + 1];
        float w0 = g_isq[s0];
        float w1 = g_isq[s1];
        const float4* p0 = reinterpret_cast<const float4*>(&g_ht[(size_t)s0 * DD]);
        const float4* p1 = reinterpret_cast<const float4*>(&g_ht[(size_t)s1 * DD]);
        #pragma unroll
        for (int j = 0; j < 4; j++) {
            float4 v0 = p0[lane + 32 * j];
            float4 v1 = p1[lane + 32 * j];
            acc[j].x += v0.x * w0 + v1.x * w1;
            acc[j].y += v0.y * w0 + v1.y * w1;
            acc[j].z += v0.z * w0 + v1.z * w1;
            acc[j].w += v0.w * w0 + v1.w * w1;
        }
    }
    if (e < e1) {
        int s0 = g_csr_src[e];
        float w0 = g_isq[s0];
        const float4* p0 = reinterpret_cast<const float4*>(&g_ht[(size_t)s0 * DD]);
        #pragma unroll
        for (int j = 0; j < 4; j++) {
            float4 v0 = p0[lane + 32 * j];
            acc[j].x += v0.x * w0;
            acc[j].y += v0.y * w0;
            acc[j].z += v0.z * w0;
            acc[j].w += v0.w * w0;
        }
    }

    float sum = 0.f, sq = 0.f;
    #pragma unroll
    for (int j = 0; j < 4; j++) {
        acc[j].x *= isq_r; acc[j].y *= isq_r;
        acc[j].z *= isq_r; acc[j].w *= isq_r;
        sum += acc[j].x + acc[j].y + acc[j].z + acc[j].w;
        sq  += acc[j].x * acc[j].x + acc[j].y * acc[j].y
             + acc[j].z * acc[j].z + acc[j].w * acc[j].w;
    }
    #pragma unroll
    for (int o = 16; o > 0; o >>= 1) {
        sum += __shfl_xor_sync(0xffffffffu, sum, o);
        sq  += __shfl_xor_sync(0xffffffffu, sq, o);
    }
    float mean = sum * (1.0f / DD);
    float var  = sq * (1.0f / DD) - mean * mean;
    float rstd = rsqrtf(var + LN_EPS);

    #pragma unroll
    for (int j = 0; j < 4; j++) {
        int col = (lane + 32 * j) * 4;
        float4 a = acc[j];
        float4 r;
        r.x = fmaxf(gamma[col + 0] * (a.x - mean) * rstd + beta[col + 0], 0.f);
        r.y = fmaxf(gamma[col + 1] * (a.y - mean) * rstd + beta[col + 1], 0.f);
        r.z = fmaxf(gamma[col + 2] * (a.z - mean) * rstd + beta[col + 2], 0.f);
        r.w = fmaxf(gamma[col + 3] * (a.w - mean) * rstd + beta[col + 3], 0.f);
        if (to_out) {
            reinterpret_cast<float4*>(&out[(size_t)row * DD])[lane + 32 * j] = r;
        } else {
            uint32_t hi0, lo0, hi1, lo1;
            bf16_split_pack(r.x, r.y, hi0, lo0);
            bf16_split_pack(r.z, r.w, hi1, lo1);
            size_t pidx = ((size_t)row * DD + col) >> 1;
            reinterpret_cast<uint32_t*>(g_a_hi)[pidx]     = hi0;
            reinterpret_cast<uint32_t*>(g_a_hi)[pidx + 1] = hi1;
            reinterpret_cast<uint32_t*>(g_a_lo)[pidx]     = lo0;
            reinterpret_cast<uint32_t*>(g_a_lo)[pidx + 1] = lo1;
        }
    }
}

// ---------------------------------------------------------------------------
extern "C" void kernel_launch(void* const* d_in, const int* in_sizes, int n_in,
                              void* d_out, int out_size) {
    const float* x      = (const float*)d_in[0];   // [NN, DD]
    const int*   edge   = (const int*)  d_in[1];   // [2, NE]
    const float* Ws     = (const float*)d_in[2];   // [NL, DD, DD]
    const float* bs     = (const float*)d_in[3];   // [NL, DD]
    const float* gammas = (const float*)d_in[4];   // [NL, DD]
    const float* betas  = (const float*)d_in[5];   // [NL, DD]
    float* out = (float*)d_out;

    const int* src = edge;
    const int* dst = edge + NE;

    cudaFuncSetAttribute(k_gemm, cudaFuncAttributeMaxDynamicSharedMemorySize, SMEM_TOT);

    // One-time conversions + graph preprocessing
    k_convW<<<NL * DD * DD / 2 / 256, 256>>>(Ws);
    k_convX<<<NN * DD / 2 / 256, 256>>>(x);
    k_deg_init<<<(NN + 255) / 256, 256>>>();
    k_deg_accum<<<(NE + 255) / 256, 256>>>(dst);
    k_isq<<<(NN + 255) / 256, 256>>>();
    k_scan1<<<SCAN_NB, 1024>>>();
    k_scan2<<<1, 64>>>();
    k_scan3<<<SCAN_NB, 1024>>>();
    k_fill<<<(NE + 255) / 256, 256>>>(src, dst);

    dim3 ggrid((NN + 127) / 128, DD / 128);
    for (int l = 0; l < NL; l++) {
        k_gemm<<<ggrid, 256, SMEM_TOT>>>(l, bs + l * DD);
        k_agg_ln<<<(NN + 7) / 8, 256>>>(gammas + l * DD, betas + l * DD,
                                        out, l == NL - 1 ? 1 : 0);
    }
}

// round 7
// speedup vs baseline: 3.4405x; 1.1499x over previous
#include <cuda_runtime.h>
#include <cuda_fp16.h>
#include <cstdint>

#define NN 50000
#define NE 800000
#define DD 512
#define NL 3
#define LN_EPS 1e-5f
#define SCAN_NB 49   // ceil(NN/1024)

// per-stage smem: A_hi 8K | A_lo 8K | B_hi 8K = 24 KB; 3 stages
#define STG_BYTES 24576
#define NSTAGE 3
#define SMEM_TOT (NSTAGE * STG_BYTES)

// Scratch (device globals — no allocation allowed)
__device__ float g_ht[NN * DD];            // GEMM output (fp32)
__device__ __half g_a_hi[NN * DD];         // layer input, fp16 high part
__device__ __half g_a_lo[NN * DD];         // layer input, fp16 low part
__device__ __half g_W_hi[NL * DD * DD];    // weights, fp16 (single term)
__device__ float g_deg[NN];
__device__ float g_isq[NN];
__device__ int   g_row_off[NN + 1];
__device__ int   g_cursor[NN];
__device__ int   g_csr_src[NE];
__device__ int   g_blksum[SCAN_NB];
__device__ int   g_blkoff[SCAN_NB];

// ---------------------------------------------------------------------------
__device__ __forceinline__ void f16_split_pack(float x, float y,
                                               uint32_t& hi, uint32_t& lo) {
    __half2 h = __floats2half2_rn(x, y);
    float rx = x - __half2float(__low2half(h));
    float ry = y - __half2float(__high2half(h));
    __half2 l = __floats2half2_rn(rx, ry);
    hi = *reinterpret_cast<uint32_t*>(&h);
    lo = *reinterpret_cast<uint32_t*>(&l);
}

__global__ void k_convW(const float* __restrict__ Ws) {
    size_t i = (size_t)blockIdx.x * 256 + threadIdx.x;   // pair index
    float2 v = reinterpret_cast<const float2*>(Ws)[i];
    __half2 h = __floats2half2_rn(v.x, v.y);
    reinterpret_cast<__half2*>(g_W_hi)[i] = h;
}

__global__ void k_convX(const float* __restrict__ x) {
    size_t i = (size_t)blockIdx.x * 256 + threadIdx.x;   // pair index
    float2 v = reinterpret_cast<const float2*>(x)[i];
    uint32_t hi, lo;
    f16_split_pack(v.x, v.y, hi, lo);
    reinterpret_cast<uint32_t*>(g_a_hi)[i] = hi;
    reinterpret_cast<uint32_t*>(g_a_lo)[i] = lo;
}

// ---------------------------------------------------------------------------
// Degree / CSR preprocessing
// ---------------------------------------------------------------------------
__global__ void k_deg_init() {
    int i = blockIdx.x * blockDim.x + threadIdx.x;
    if (i < NN) g_deg[i] = 1.0f;
}
__global__ void k_deg_accum(const int* __restrict__ dst) {
    int e = blockIdx.x * blockDim.x + threadIdx.x;
    if (e < NE) atomicAdd(&g_deg[dst[e]], 1.0f);
}
__global__ void k_isq() {
    int i = blockIdx.x * blockDim.x + threadIdx.x;
    if (i < NN) g_isq[i] = rsqrtf(g_deg[i]);
}

__global__ void k_scan1() {
    __shared__ int wsum[32];
    int b = blockIdx.x, t = threadIdx.x, w = t >> 5, l = t & 31;
    int idx = b * 1024 + t;
    int c = (idx < NN) ? (int)(g_deg[idx] - 1.0f) : 0;
    int incl = c;
    #pragma unroll
    for (int o = 1; o < 32; o <<= 1) {
        int v = __shfl_up_sync(0xffffffffu, incl, o);
        if (l >= o) incl += v;
    }
    if (l == 31) wsum[w] = incl;
    __syncthreads();
    if (w == 0) {
        int v = wsum[l];
        #pragma unroll
        for (int o = 1; o < 32; o <<= 1) {
            int u = __shfl_up_sync(0xffffffffu, v, o);
            if (l >= o) v += u;
        }
        wsum[l] = v;
    }
    __syncthreads();
    int excl = (w ? wsum[w - 1] : 0) + incl - c;
    if (idx < NN) g_row_off[idx] = excl;
    if (t == 1023) g_blksum[b] = wsum[31];
}

__global__ void k_scan2() {
    int t = threadIdx.x, l = t & 31, w = t >> 5;
    __shared__ int ws[2];
    int v = (t < SCAN_NB) ? g_blksum[t] : 0;
    int incl = v;
    #pragma unroll
    for (int o = 1; o < 32; o <<= 1) {
        int u = __shfl_up_sync(0xffffffffu, incl, o);
        if (l >= o) incl += u;
    }
    if (l == 31) ws[w] = incl;
    __syncthreads();
    int inclusive = incl + (w == 1 ? ws[0] : 0);
    if (t < SCAN_NB) g_blkoff[t] = inclusive - v;
    if (t == SCAN_NB - 1) g_row_off[NN] = inclusive;
}

__global__ void k_scan3() {
    int b = blockIdx.x;
    int idx = b * 1024 + threadIdx.x;
    if (idx < NN) {
        int v = g_row_off[idx] + g_blkoff[b];
        g_row_off[idx] = v;
        g_cursor[idx]  = v;
    }
}

__global__ void k_fill(const int* __restrict__ src, const int* __restrict__ dst) {
    int e = blockIdx.x * blockDim.x + threadIdx.x;
    if (e < NE) {
        int p = atomicAdd(&g_cursor[dst[e]], 1);
        g_csr_src[p] = src[e];
    }
}

// ---------------------------------------------------------------------------
// Tensor-core GEMM, fp16 2-term split: acc += Ah*Bh + Al*Bh.
// BM=128, BN=128, BK=32; 8 warps (4m x 2n), 32x64/warp; 3-stage cp.async.
// ---------------------------------------------------------------------------
__device__ __forceinline__ uint32_t swzA(uint32_t a) { return a ^ ((a >> 3) & 0x30); }
__device__ __forceinline__ uint32_t swzB(uint32_t a) { return a ^ ((a >> 4) & 0x70); }

__device__ __forceinline__ void cpa16(uint32_t s, const void* g, int sz) {
    asm volatile("cp.async.cg.shared.global [%0], [%1], 16, %2;"
                 :: "r"(s), "l"(g), "r"(sz));
}
__device__ __forceinline__ void ldsm_x4(uint32_t* r, uint32_t addr) {
    asm volatile("ldmatrix.sync.aligned.m8n8.x4.shared.b16 {%0,%1,%2,%3}, [%4];"
                 : "=r"(r[0]), "=r"(r[1]), "=r"(r[2]), "=r"(r[3]) : "r"(addr));
}
__device__ __forceinline__ void ldsm_x4_t(uint32_t* r, uint32_t addr) {
    asm volatile("ldmatrix.sync.aligned.m8n8.x4.trans.shared.b16 {%0,%1,%2,%3}, [%4];"
                 : "=r"(r[0]), "=r"(r[1]), "=r"(r[2]), "=r"(r[3]) : "r"(addr));
}
__device__ __forceinline__ void mma16816(float* c, const uint32_t* a, const uint32_t* b) {
    asm volatile("mma.sync.aligned.m16n8k16.row.col.f32.f16.f16.f32 "
                 "{%0,%1,%2,%3}, {%4,%5,%6,%7}, {%8,%9}, {%0,%1,%2,%3};"
                 : "+f"(c[0]), "+f"(c[1]), "+f"(c[2]), "+f"(c[3])
                 : "r"(a[0]), "r"(a[1]), "r"(a[2]), "r"(a[3]), "r"(b[0]), "r"(b[1]));
}

__global__ __launch_bounds__(256, 2) void k_gemm(int l, const float* __restrict__ bias) {
    extern __shared__ __align__(128) unsigned char sm[];
    uint32_t sbase = (uint32_t)__cvta_generic_to_shared(sm);

    const __half* __restrict__ Ahi = g_a_hi;
    const __half* __restrict__ Alo = g_a_lo;
    const __half* __restrict__ Whi = g_W_hi + (size_t)l * DD * DD;

    int t = threadIdx.x;
    int lane = t & 31;
    int warp = t >> 5;
    int m0 = blockIdx.x * 128;
    int n0 = blockIdx.y * 128;
    int wm = (warp & 3) * 32;
    int wn = (warp >> 2) * 64;

    float acc[2][8][4];
    #pragma unroll
    for (int i = 0; i < 2; i++)
        #pragma unroll
        for (int j = 0; j < 8; j++)
            #pragma unroll
            for (int q = 0; q < 4; q++) acc[i][j][q] = 0.f;

    // cp.async load mappings
    int aRow = t >> 2;          // 0..63, +64*h
    int aU   = (t & 3);         // 16B unit within 64B row
    int bRow = t >> 3;          // 0..31
    int bU   = (t & 7);         // pair of 16B units within 256B row

    auto issue = [&](int kb) {
        uint32_t so = sbase + (uint32_t)(kb % NSTAGE) * STG_BYTES;
        #pragma unroll
        for (int h = 0; h < 2; h++) {
            int r = aRow + 64 * h;
            int gr = m0 + r;
            int sz = (gr < NN) ? 16 : 0;
            size_t gidx = (size_t)(gr < NN ? gr : 0) * DD + kb * 32 + aU * 8;
            uint32_t ad = swzA((uint32_t)r * 64 + aU * 16);
            cpa16(so + ad, &Ahi[gidx], sz);
            cpa16(so + 8192 + ad, &Alo[gidx], sz);
        }
        #pragma unroll
        for (int u = 0; u < 2; u++) {
            size_t gidx = (size_t)(kb * 32 + bRow) * DD + n0 + bU * 16 + u * 8;
            uint32_t bd = swzB((uint32_t)bRow * 256 + bU * 32 + u * 16);
            cpa16(so + 16384 + bd, &Whi[gidx], 16);
        }
    };

    const int NIT = DD / 32;  // 16
    issue(0);
    asm volatile("cp.async.commit_group;");
    issue(1);
    asm volatile("cp.async.commit_group;");

    for (int kb = 0; kb < NIT; kb++) {
        if (kb + 2 < NIT) {
            issue(kb + 2);
            asm volatile("cp.async.commit_group;");
            asm volatile("cp.async.wait_group 2;");
        } else if (kb + 2 == NIT) {
            asm volatile("cp.async.wait_group 1;");
        } else {
            asm volatile("cp.async.wait_group 0;");
        }
        __syncthreads();

        uint32_t so = sbase + (uint32_t)(kb % NSTAGE) * STG_BYTES;
        uint32_t sA_hi = so, sA_lo = so + 8192, sB_hi = so + 16384;

        #pragma unroll
        for (int ks = 0; ks < 2; ks++) {
            int k = ks * 16;
            uint32_t ah[2][4], al[2][4];
            #pragma unroll
            for (int mi = 0; mi < 2; mi++) {
                uint32_t ad = (uint32_t)(wm + mi * 16 + (lane & 15)) * 64
                            + (uint32_t)(k + 8 * (lane >> 4)) * 2;
                ldsm_x4(ah[mi], sA_hi + swzA(ad));
                ldsm_x4(al[mi], sA_lo + swzA(ad));
            }
            #pragma unroll
            for (int nj = 0; nj < 4; nj++) {
                uint32_t bh[4];
                uint32_t bd = (uint32_t)(k + (lane & 15)) * 256
                            + (uint32_t)(wn + nj * 16 + 8 * (lane >> 4)) * 2;
                ldsm_x4_t(bh, sB_hi + swzB(bd));
                #pragma unroll
                for (int mi = 0; mi < 2; mi++)
                    #pragma unroll
                    for (int hf = 0; hf < 2; hf++)
                        mma16816(acc[mi][nj * 2 + hf], ah[mi], bh + 2 * hf);
                #pragma unroll
                for (int mi = 0; mi < 2; mi++)
                    #pragma unroll
                    for (int hf = 0; hf < 2; hf++)
                        mma16816(acc[mi][nj * 2 + hf], al[mi], bh + 2 * hf);
            }
        }
        __syncthreads();
    }

    // Epilogue: add bias, store fp32
    #pragma unroll
    for (int mi = 0; mi < 2; mi++) {
        #pragma unroll
        for (int nf = 0; nf < 8; nf++) {
            int row = m0 + wm + mi * 16 + (lane >> 2);
            int col = n0 + wn + nf * 8 + (lane & 3) * 2;
            float b0 = bias[col], b1 = bias[col + 1];
            float* c = acc[mi][nf];
            if (row < NN) {
                float2 v = make_float2(c[0] + b0, c[1] + b1);
                *reinterpret_cast<float2*>(&g_ht[(size_t)row * DD + col]) = v;
            }
            if (row + 8 < NN) {
                float2 v = make_float2(c[2] + b0, c[3] + b1);
                *reinterpret_cast<float2*>(&g_ht[(size_t)(row + 8) * DD + col]) = v;
            }
        }
    }
}

// ---------------------------------------------------------------------------
// FUSED: CSR gather-aggregate + self-loop + LayerNorm + ReLU.
// ---------------------------------------------------------------------------
__global__ __launch_bounds__(256) void k_agg_ln(const float* __restrict__ gamma,
                                                const float* __restrict__ beta,
                                                float* __restrict__ out, int to_out) {
    int row = blockIdx.x * 8 + (threadIdx.x >> 5);
    if (row >= NN) return;
    int lane = threadIdx.x & 31;

    float isq_r = g_isq[row];

    const float4* ph = reinterpret_cast<const float4*>(&g_ht[(size_t)row * DD]);
    float4 acc[4];
    #pragma unroll
    for (int j = 0; j < 4; j++) {
        float4 v = ph[lane + 32 * j];
        acc[j].x = v.x * isq_r; acc[j].y = v.y * isq_r;
        acc[j].z = v.z * isq_r; acc[j].w = v.w * isq_r;
    }

    int e  = g_row_off[row];
    int e1 = g_row_off[row + 1];
    for (; e + 1 < e1; e += 2) {
        int s0 = g_csr_src[e];
        int s1 = g_csr_src[e + 1];
        float w0 = g_isq[s0];
        float w1 = g_isq[s1];
        const float4* p0 = reinterpret_cast<const float4*>(&g_ht[(size_t)s0 * DD]);
        const float4* p1 = reinterpret_cast<const float4*>(&g_ht[(size_t)s1 * DD]);
        #pragma unroll
        for (int j = 0; j < 4; j++) {
            float4 v0 = p0[lane + 32 * j];
            float4 v1 = p1[lane + 32 * j];
            acc[j].x += v0.x * w0 + v1.x * w1;
            acc[j].y += v0.y * w0 + v1.y * w1;
            acc[j].z += v0.z * w0 + v1.z * w1;
            acc[j].w += v0.w * w0 + v1.w * w1;
        }
    }
    if (e < e1) {
        int s0 = g_csr_src[e];
        float w0 = g_isq[s0];
        const float4* p0 = reinterpret_cast<const float4*>(&g_ht[(size_t)s0 * DD]);
        #pragma unroll
        for (int j = 0; j < 4; j++) {
            float4 v0 = p0[lane + 32 * j];
            acc[j].x += v0.x * w0;
            acc[j].y += v0.y * w0;
            acc[j].z += v0.z * w0;
            acc[j].w += v0.w * w0;
        }
    }

    float sum = 0.f, sq = 0.f;
    #pragma unroll
    for (int j = 0; j < 4; j++) {
        acc[j].x *= isq_r; acc[j].y *= isq_r;
        acc[j].z *= isq_r; acc[j].w *= isq_r;
        sum += acc[j].x + acc[j].y + acc[j].z + acc[j].w;
        sq  += acc[j].x * acc[j].x + acc[j].y * acc[j].y
             + acc[j].z * acc[j].z + acc[j].w * acc[j].w;
    }
    #pragma unroll
    for (int o = 16; o > 0; o >>= 1) {
        sum += __shfl_xor_sync(0xffffffffu, sum, o);
        sq  += __shfl_xor_sync(0xffffffffu, sq, o);
    }
    float mean = sum * (1.0f / DD);
    float var  = sq * (1.0f / DD) - mean * mean;
    float rstd = rsqrtf(var + LN_EPS);

    #pragma unroll
    for (int j = 0; j < 4; j++) {
        int col = (lane + 32 * j) * 4;
        float4 a = acc[j];
        float4 r;
        r.x = fmaxf(gamma[col + 0] * (a.x - mean) * rstd + beta[col + 0], 0.f);
        r.y = fmaxf(gamma[col + 1] * (a.y - mean) * rstd + beta[col + 1], 0.f);
        r.z = fmaxf(gamma[col + 2] * (a.z - mean) * rstd + beta[col + 2], 0.f);
        r.w = fmaxf(gamma[col + 3] * (a.w - mean) * rstd + beta[col + 3], 0.f);
        if (to_out) {
            reinterpret_cast<float4*>(&out[(size_t)row * DD])[lane + 32 * j] = r;
        } else {
            uint32_t hi0, lo0, hi1, lo1;
            f16_split_pack(r.x, r.y, hi0, lo0);
            f16_split_pack(r.z, r.w, hi1, lo1);
            size_t pidx = ((size_t)row * DD + col) >> 1;
            reinterpret_cast<uint32_t*>(g_a_hi)[pidx]     = hi0;
            reinterpret_cast<uint32_t*>(g_a_hi)[pidx + 1] = hi1;
            reinterpret_cast<uint32_t*>(g_a_lo)[pidx]     = lo0;
            reinterpret_cast<uint32_t*>(g_a_lo)[pidx + 1] = lo1;
        }
    }
}

// ---------------------------------------------------------------------------
extern "C" void kernel_launch(void* const* d_in, const int* in_sizes, int n_in,
                              void* d_out, int out_size) {
    const float* x      = (const float*)d_in[0];   // [NN, DD]
    const int*   edge   = (const int*)  d_in[1];   // [2, NE]
    const float* Ws     = (const float*)d_in[2];   // [NL, DD, DD]
    const float* bs     = (const float*)d_in[3];   // [NL, DD]
    const float* gammas = (const float*)d_in[4];   // [NL, DD]
    const float* betas  = (const float*)d_in[5];   // [NL, DD]
    float* out = (float*)d_out;

    const int* src = edge;
    const int* dst = edge + NE;

    cudaFuncSetAttribute(k_gemm, cudaFuncAttributeMaxDynamicSharedMemorySize, SMEM_TOT);

    // One-time conversions + graph preprocessing
    k_convW<<<NL * DD * DD / 2 / 256, 256>>>(Ws);
    k_convX<<<NN * DD / 2 / 256, 256>>>(x);
    k_deg_init<<<(NN + 255) / 256, 256>>>();
    k_deg_accum<<<(NE + 255) / 256, 256>>>(dst);
    k_isq<<<(NN + 255) / 256, 256>>>();
    k_scan1<<<SCAN_NB, 1024>>>();
    k_scan2<<<1, 64>>>();
    k_scan3<<<SCAN_NB, 1024>>>();
    k_fill<<<(NE + 255) / 256, 256>>>(src, dst);

    dim3 ggrid((NN + 127) / 128, DD / 128);
    for (int l = 0; l < NL; l++) {
        k_gemm<<<ggrid, 256, SMEM_TOT>>>(l, bs + l * DD);
        k_agg_ln<<<(NN + 7) / 8, 256>>>(gammas + l * DD, betas + l * DD,
                                        out, l == NL - 1 ? 1 : 0);
    }
}

// round 8
// speedup vs baseline: 4.0201x; 1.1685x over previous
#include <cuda_runtime.h>
#include <cuda_fp16.h>
#include <cstdint>

#define NN 50000
#define NE 800000
#define DD 512
#define NL 3
#define LN_EPS 1e-5f
#define SCAN_NB 49   // ceil(NN/1024)

// per-stage smem: A_hi 8K | A_lo 8K | B_hi 8K = 24 KB; 3 stages
#define STG_BYTES 24576
#define NSTAGE 3
#define SMEM_TOT (NSTAGE * STG_BYTES)

// Scratch (device globals — no allocation allowed)
__device__ __half g_ht[NN * DD];           // GEMM output (fp16 storage)
__device__ __half g_a_hi[NN * DD];         // layer input, fp16 high part
__device__ __half g_a_lo[NN * DD];         // layer input, fp16 low part
__device__ __half g_W_hi[NL * DD * DD];    // weights, fp16 (single term)
__device__ float g_deg[NN];
__device__ float g_isq[NN];
__device__ int   g_row_off[NN + 1];
__device__ int   g_cursor[NN];
__device__ int   g_csr_src[NE];
__device__ int   g_blksum[SCAN_NB];
__device__ int   g_blkoff[SCAN_NB];

// ---------------------------------------------------------------------------
__device__ __forceinline__ void f16_split_pack(float x, float y,
                                               uint32_t& hi, uint32_t& lo) {
    __half2 h = __floats2half2_rn(x, y);
    float rx = x - __half2float(__low2half(h));
    float ry = y - __half2float(__high2half(h));
    __half2 l = __floats2half2_rn(rx, ry);
    hi = *reinterpret_cast<uint32_t*>(&h);
    lo = *reinterpret_cast<uint32_t*>(&l);
}

__global__ void k_convW(const float* __restrict__ Ws) {
    size_t i = (size_t)blockIdx.x * 256 + threadIdx.x;   // pair index
    float2 v = reinterpret_cast<const float2*>(Ws)[i];
    __half2 h = __floats2half2_rn(v.x, v.y);
    reinterpret_cast<__half2*>(g_W_hi)[i] = h;
}

__global__ void k_convX(const float* __restrict__ x) {
    size_t i = (size_t)blockIdx.x * 256 + threadIdx.x;   // pair index
    float2 v = reinterpret_cast<const float2*>(x)[i];
    uint32_t hi, lo;
    f16_split_pack(v.x, v.y, hi, lo);
    reinterpret_cast<uint32_t*>(g_a_hi)[i] = hi;
    reinterpret_cast<uint32_t*>(g_a_lo)[i] = lo;
}

// ---------------------------------------------------------------------------
// Degree / CSR preprocessing
// ---------------------------------------------------------------------------
__global__ void k_deg_init() {
    int i = blockIdx.x * blockDim.x + threadIdx.x;
    if (i < NN) g_deg[i] = 1.0f;
}
__global__ void k_deg_accum(const int* __restrict__ dst) {
    int e = blockIdx.x * blockDim.x + threadIdx.x;
    if (e < NE) atomicAdd(&g_deg[dst[e]], 1.0f);
}
__global__ void k_isq() {
    int i = blockIdx.x * blockDim.x + threadIdx.x;
    if (i < NN) g_isq[i] = rsqrtf(g_deg[i]);
}

__global__ void k_scan1() {
    __shared__ int wsum[32];
    int b = blockIdx.x, t = threadIdx.x, w = t >> 5, l = t & 31;
    int idx = b * 1024 + t;
    int c = (idx < NN) ? (int)(g_deg[idx] - 1.0f) : 0;
    int incl = c;
    #pragma unroll
    for (int o = 1; o < 32; o <<= 1) {
        int v = __shfl_up_sync(0xffffffffu, incl, o);
        if (l >= o) incl += v;
    }
    if (l == 31) wsum[w] = incl;
    __syncthreads();
    if (w == 0) {
        int v = wsum[l];
        #pragma unroll
        for (int o = 1; o < 32; o <<= 1) {
            int u = __shfl_up_sync(0xffffffffu, v, o);
            if (l >= o) v += u;
        }
        wsum[l] = v;
    }
    __syncthreads();
    int excl = (w ? wsum[w - 1] : 0) + incl - c;
    if (idx < NN) g_row_off[idx] = excl;
    if (t == 1023) g_blksum[b] = wsum[31];
}

__global__ void k_scan2() {
    int t = threadIdx.x, l = t & 31, w = t >> 5;
    __shared__ int ws[2];
    int v = (t < SCAN_NB) ? g_blksum[t] : 0;
    int incl = v;
    #pragma unroll
    for (int o = 1; o < 32; o <<= 1) {
        int u = __shfl_up_sync(0xffffffffu, incl, o);
        if (l >= o) incl += u;
    }
    if (l == 31) ws[w] = incl;
    __syncthreads();
    int inclusive = incl + (w == 1 ? ws[0] : 0);
    if (t < SCAN_NB) g_blkoff[t] = inclusive - v;
    if (t == SCAN_NB - 1) g_row_off[NN] = inclusive;
}

__global__ void k_scan3() {
    int b = blockIdx.x;
    int idx = b * 1024 + threadIdx.x;
    if (idx < NN) {
        int v = g_row_off[idx] + g_blkoff[b];
        g_row_off[idx] = v;
        g_cursor[idx]  = v;
    }
}

__global__ void k_fill(const int* __restrict__ src, const int* __restrict__ dst) {
    int e = blockIdx.x * blockDim.x + threadIdx.x;
    if (e < NE) {
        int p = atomicAdd(&g_cursor[dst[e]], 1);
        g_csr_src[p] = src[e];
    }
}

// ---------------------------------------------------------------------------
// Tensor-core GEMM, fp16 2-term split: acc += Ah*Bh + Al*Bh.
// BM=128, BN=128, BK=32; 8 warps (4m x 2n), 32x64/warp; 3-stage cp.async.
// Output stored as fp16.
// ---------------------------------------------------------------------------
__device__ __forceinline__ uint32_t swzA(uint32_t a) { return a ^ ((a >> 3) & 0x30); }
__device__ __forceinline__ uint32_t swzB(uint32_t a) { return a ^ ((a >> 4) & 0x70); }

__device__ __forceinline__ void cpa16(uint32_t s, const void* g, int sz) {
    asm volatile("cp.async.cg.shared.global [%0], [%1], 16, %2;"
                 :: "r"(s), "l"(g), "r"(sz));
}
__device__ __forceinline__ void ldsm_x4(uint32_t* r, uint32_t addr) {
    asm volatile("ldmatrix.sync.aligned.m8n8.x4.shared.b16 {%0,%1,%2,%3}, [%4];"
                 : "=r"(r[0]), "=r"(r[1]), "=r"(r[2]), "=r"(r[3]) : "r"(addr));
}
__device__ __forceinline__ void ldsm_x4_t(uint32_t* r, uint32_t addr) {
    asm volatile("ldmatrix.sync.aligned.m8n8.x4.trans.shared.b16 {%0,%1,%2,%3}, [%4];"
                 : "=r"(r[0]), "=r"(r[1]), "=r"(r[2]), "=r"(r[3]) : "r"(addr));
}
__device__ __forceinline__ void mma16816(float* c, const uint32_t* a, const uint32_t* b) {
    asm volatile("mma.sync.aligned.m16n8k16.row.col.f32.f16.f16.f32 "
                 "{%0,%1,%2,%3}, {%4,%5,%6,%7}, {%8,%9}, {%0,%1,%2,%3};"
                 : "+f"(c[0]), "+f"(c[1]), "+f"(c[2]), "+f"(c[3])
                 : "r"(a[0]), "r"(a[1]), "r"(a[2]), "r"(a[3]), "r"(b[0]), "r"(b[1]));
}

__global__ __launch_bounds__(256, 2) void k_gemm(int l, const float* __restrict__ bias) {
    extern __shared__ __align__(128) unsigned char sm[];
    uint32_t sbase = (uint32_t)__cvta_generic_to_shared(sm);

    const __half* __restrict__ Ahi = g_a_hi;
    const __half* __restrict__ Alo = g_a_lo;
    const __half* __restrict__ Whi = g_W_hi + (size_t)l * DD * DD;

    int t = threadIdx.x;
    int lane = t & 31;
    int warp = t >> 5;
    int m0 = blockIdx.x * 128;
    int n0 = blockIdx.y * 128;
    int wm = (warp & 3) * 32;
    int wn = (warp >> 2) * 64;

    float acc[2][8][4];
    #pragma unroll
    for (int i = 0; i < 2; i++)
        #pragma unroll
        for (int j = 0; j < 8; j++)
            #pragma unroll
            for (int q = 0; q < 4; q++) acc[i][j][q] = 0.f;

    // cp.async load mappings
    int aRow = t >> 2;          // 0..63, +64*h
    int aU   = (t & 3);         // 16B unit within 64B row
    int bRow = t >> 3;          // 0..31
    int bU   = (t & 7);         // pair of 16B units within 256B row

    auto issue = [&](int kb) {
        uint32_t so = sbase + (uint32_t)(kb % NSTAGE) * STG_BYTES;
        #pragma unroll
        for (int h = 0; h < 2; h++) {
            int r = aRow + 64 * h;
            int gr = m0 + r;
            int sz = (gr < NN) ? 16 : 0;
            size_t gidx = (size_t)(gr < NN ? gr : 0) * DD + kb * 32 + aU * 8;
            uint32_t ad = swzA((uint32_t)r * 64 + aU * 16);
            cpa16(so + ad, &Ahi[gidx], sz);
            cpa16(so + 8192 + ad, &Alo[gidx], sz);
        }
        #pragma unroll
        for (int u = 0; u < 2; u++) {
            size_t gidx = (size_t)(kb * 32 + bRow) * DD + n0 + bU * 16 + u * 8;
            uint32_t bd = swzB((uint32_t)bRow * 256 + bU * 32 + u * 16);
            cpa16(so + 16384 + bd, &Whi[gidx], 16);
        }
    };

    const int NIT = DD / 32;  // 16
    issue(0);
    asm volatile("cp.async.commit_group;");
    issue(1);
    asm volatile("cp.async.commit_group;");

    for (int kb = 0; kb < NIT; kb++) {
        if (kb + 2 < NIT) {
            issue(kb + 2);
            asm volatile("cp.async.commit_group;");
            asm volatile("cp.async.wait_group 2;");
        } else if (kb + 2 == NIT) {
            asm volatile("cp.async.wait_group 1;");
        } else {
            asm volatile("cp.async.wait_group 0;");
        }
        __syncthreads();

        uint32_t so = sbase + (uint32_t)(kb % NSTAGE) * STG_BYTES;
        uint32_t sA_hi = so, sA_lo = so + 8192, sB_hi = so + 16384;

        #pragma unroll
        for (int ks = 0; ks < 2; ks++) {
            int k = ks * 16;
            uint32_t ah[2][4], al[2][4];
            #pragma unroll
            for (int mi = 0; mi < 2; mi++) {
                uint32_t ad = (uint32_t)(wm + mi * 16 + (lane & 15)) * 64
                            + (uint32_t)(k + 8 * (lane >> 4)) * 2;
                ldsm_x4(ah[mi], sA_hi + swzA(ad));
                ldsm_x4(al[mi], sA_lo + swzA(ad));
            }
            #pragma unroll
            for (int nj = 0; nj < 4; nj++) {
                uint32_t bh[4];
                uint32_t bd = (uint32_t)(k + (lane & 15)) * 256
                            + (uint32_t)(wn + nj * 16 + 8 * (lane >> 4)) * 2;
                ldsm_x4_t(bh, sB_hi + swzB(bd));
                #pragma unroll
                for (int mi = 0; mi < 2; mi++)
                    #pragma unroll
                    for (int hf = 0; hf < 2; hf++)
                        mma16816(acc[mi][nj * 2 + hf], ah[mi], bh + 2 * hf);
                #pragma unroll
                for (int mi = 0; mi < 2; mi++)
                    #pragma unroll
                    for (int hf = 0; hf < 2; hf++)
                        mma16816(acc[mi][nj * 2 + hf], al[mi], bh + 2 * hf);
            }
        }
        __syncthreads();
    }

    // Epilogue: add bias, store fp16
    #pragma unroll
    for (int mi = 0; mi < 2; mi++) {
        #pragma unroll
        for (int nf = 0; nf < 8; nf++) {
            int row = m0 + wm + mi * 16 + (lane >> 2);
            int col = n0 + wn + nf * 8 + (lane & 3) * 2;
            float b0 = bias[col], b1 = bias[col + 1];
            float* c = acc[mi][nf];
            if (row < NN) {
                __half2 h = __floats2half2_rn(c[0] + b0, c[1] + b1);
                *reinterpret_cast<__half2*>(&g_ht[(size_t)row * DD + col]) = h;
            }
            if (row + 8 < NN) {
                __half2 h = __floats2half2_rn(c[2] + b0, c[3] + b1);
                *reinterpret_cast<__half2*>(&g_ht[(size_t)(row + 8) * DD + col]) = h;
            }
        }
    }
}

// ---------------------------------------------------------------------------
// FUSED: CSR gather-aggregate + self-loop + LayerNorm + ReLU.
// Gathers fp16 rows (16B = 8 halves per lane-chunk), accumulates in fp32.
// Each lane owns 16 columns: chunks (lane + 32*j)*8, j in {0,1}.
// ---------------------------------------------------------------------------
__device__ __forceinline__ void acc_row8(float* a, uint4 v, float w) {
    float2 f0 = __half22float2(*reinterpret_cast<__half2*>(&v.x));
    float2 f1 = __half22float2(*reinterpret_cast<__half2*>(&v.y));
    float2 f2 = __half22float2(*reinterpret_cast<__half2*>(&v.z));
    float2 f3 = __half22float2(*reinterpret_cast<__half2*>(&v.w));
    a[0] += f0.x * w; a[1] += f0.y * w;
    a[2] += f1.x * w; a[3] += f1.y * w;
    a[4] += f2.x * w; a[5] += f2.y * w;
    a[6] += f3.x * w; a[7] += f3.y * w;
}

__global__ __launch_bounds__(256) void k_agg_ln(const float* __restrict__ gamma,
                                                const float* __restrict__ beta,
                                                float* __restrict__ out, int to_out) {
    int row = blockIdx.x * 8 + (threadIdx.x >> 5);
    if (row >= NN) return;
    int lane = threadIdx.x & 31;

    float isq_r = g_isq[row];

    float acc[2][8];
    {
        const uint4* ph = reinterpret_cast<const uint4*>(&g_ht[(size_t)row * DD]);
        #pragma unroll
        for (int j = 0; j < 2; j++) {
            #pragma unroll
            for (int q = 0; q < 8; q++) acc[j][q] = 0.f;
            acc_row8(acc[j], ph[lane + 32 * j], isq_r);
        }
    }

    int e  = g_row_off[row];
    int e1 = g_row_off[row + 1];
    for (; e + 1 < e1; e += 2) {
        int s0 = g_csr_src[e];
        int s1 = g_csr_src[e + 1];
        float w0 = g_isq[s0];
        float w1 = g_isq[s1];
        const uint4* p0 = reinterpret_cast<const uint4*>(&g_ht[(size_t)s0 * DD]);
        const uint4* p1 = reinterpret_cast<const uint4*>(&g_ht[(size_t)s1 * DD]);
        #pragma unroll
        for (int j = 0; j < 2; j++) {
            uint4 v0 = p0[lane + 32 * j];
            uint4 v1 = p1[lane + 32 * j];
            acc_row8(acc[j], v0, w0);
            acc_row8(acc[j], v1, w1);
        }
    }
    if (e < e1) {
        int s0 = g_csr_src[e];
        float w0 = g_isq[s0];
        const uint4* p0 = reinterpret_cast<const uint4*>(&g_ht[(size_t)s0 * DD]);
        #pragma unroll
        for (int j = 0; j < 2; j++)
            acc_row8(acc[j], p0[lane + 32 * j], w0);
    }

    float sum = 0.f, sq = 0.f;
    #pragma unroll
    for (int j = 0; j < 2; j++)
        #pragma unroll
        for (int q = 0; q < 8; q++) {
            acc[j][q] *= isq_r;
            sum += acc[j][q];
            sq  += acc[j][q] * acc[j][q];
        }
    #pragma unroll
    for (int o = 16; o > 0; o >>= 1) {
        sum += __shfl_xor_sync(0xffffffffu, sum, o);
        sq  += __shfl_xor_sync(0xffffffffu, sq, o);
    }
    float mean = sum * (1.0f / DD);
    float var  = sq * (1.0f / DD) - mean * mean;
    float rstd = rsqrtf(var + LN_EPS);

    #pragma unroll
    for (int j = 0; j < 2; j++) {
        int col = (lane + 32 * j) * 8;
        float r[8];
        #pragma unroll
        for (int q = 0; q < 8; q++)
            r[q] = fmaxf(gamma[col + q] * (acc[j][q] - mean) * rstd + beta[col + q], 0.f);
        if (to_out) {
            float4* po = reinterpret_cast<float4*>(&out[(size_t)row * DD + col]);
            po[0] = make_float4(r[0], r[1], r[2], r[3]);
            po[1] = make_float4(r[4], r[5], r[6], r[7]);
        } else {
            size_t pidx = ((size_t)row * DD + col) >> 1;
            #pragma unroll
            for (int q = 0; q < 4; q++) {
                uint32_t hi, lo;
                f16_split_pack(r[2 * q], r[2 * q + 1], hi, lo);
                reinterpret_cast<uint32_t*>(g_a_hi)[pidx + q] = hi;
                reinterpret_cast<uint32_t*>(g_a_lo)[pidx + q] = lo;
            }
        }
    }
}

// ---------------------------------------------------------------------------
extern "C" void kernel_launch(void* const* d_in, const int* in_sizes, int n_in,
                              void* d_out, int out_size) {
    const float* x      = (const float*)d_in[0];   // [NN, DD]
    const int*   edge   = (const int*)  d_in[1];   // [2, NE]
    const float* Ws     = (const float*)d_in[2];   // [NL, DD, DD]
    const float* bs     = (const float*)d_in[3];   // [NL, DD]
    const float* gammas = (const float*)d_in[4];   // [NL, DD]
    const float* betas  = (const float*)d_in[5];   // [NL, DD]
    float* out = (float*)d_out;

    const int* src = edge;
    const int* dst = edge + NE;

    cudaFuncSetAttribute(k_gemm, cudaFuncAttributeMaxDynamicSharedMemorySize, SMEM_TOT);

    // One-time conversions + graph preprocessing
    k_convW<<<NL * DD * DD / 2 / 256, 256>>>(Ws);
    k_convX<<<NN * DD / 2 / 256, 256>>>(x);
    k_deg_init<<<(NN + 255) / 256, 256>>>();
    k_deg_accum<<<(NE + 255) / 256, 256>>>(dst);
    k_isq<<<(NN + 255) / 256, 256>>>();
    k_scan1<<<SCAN_NB, 1024>>>();
    k_scan2<<<1, 64>>>();
    k_scan3<<<SCAN_NB, 1024>>>();
    k_fill<<<(NE + 255) / 256, 256>>>(src, dst);

    dim3 ggrid((NN + 127) / 128, DD / 128);
    for (int l = 0; l < NL; l++) {
        k_gemm<<<ggrid, 256, SMEM_TOT>>>(l, bs + l * DD);
        k_agg_ln<<<(NN + 7) / 8, 256>>>(gammas + l * DD, betas + l * DD,
                                        out, l == NL - 1 ? 1 : 0);
    }
}

// round 9
// speedup vs baseline: 5.2738x; 1.3119x over previous
#include <cuda_runtime.h>
#include <cuda_fp16.h>
#include <cstdint>

#define NN 50000
#define NE 800000
#define DD 512
#define NL 3
#define LN_EPS 1e-5f
#define SCAN_NB 49   // ceil(NN/1024)

// per-stage smem: A 8K | B 8K = 16 KB; 3 stages
#define STG_BYTES 16384
#define NSTAGE 3
#define SMEM_TOT (NSTAGE * STG_BYTES)

// Scratch (device globals — no allocation allowed)
__device__ __half g_ht[NN * DD];           // GEMM output (fp16 storage)
__device__ __half g_a[NN * DD];            // layer input (fp16)
__device__ __half g_W[NL * DD * DD];       // weights (fp16)
__device__ float g_deg[NN];
__device__ float g_isq[NN];
__device__ int   g_row_off[NN + 1];
__device__ int   g_cursor[NN];
__device__ int   g_csr_src[NE];
__device__ int   g_blksum[SCAN_NB];
__device__ int   g_blkoff[SCAN_NB];

// ---------------------------------------------------------------------------
__global__ void k_convW(const float* __restrict__ Ws) {
    size_t i = (size_t)blockIdx.x * 256 + threadIdx.x;   // pair index
    float2 v = reinterpret_cast<const float2*>(Ws)[i];
    reinterpret_cast<__half2*>(g_W)[i] = __floats2half2_rn(v.x, v.y);
}

__global__ void k_convX(const float* __restrict__ x) {
    size_t i = (size_t)blockIdx.x * 256 + threadIdx.x;   // pair index
    float2 v = reinterpret_cast<const float2*>(x)[i];
    reinterpret_cast<__half2*>(g_a)[i] = __floats2half2_rn(v.x, v.y);
}

// ---------------------------------------------------------------------------
// Degree / CSR preprocessing
// ---------------------------------------------------------------------------
__global__ void k_deg_init() {
    int i = blockIdx.x * blockDim.x + threadIdx.x;
    if (i < NN) g_deg[i] = 1.0f;
}
__global__ void k_deg_accum(const int* __restrict__ dst) {
    int e = blockIdx.x * blockDim.x + threadIdx.x;
    if (e < NE) atomicAdd(&g_deg[dst[e]], 1.0f);
}
__global__ void k_isq() {
    int i = blockIdx.x * blockDim.x + threadIdx.x;
    if (i < NN) g_isq[i] = rsqrtf(g_deg[i]);
}

__global__ void k_scan1() {
    __shared__ int wsum[32];
    int b = blockIdx.x, t = threadIdx.x, w = t >> 5, l = t & 31;
    int idx = b * 1024 + t;
    int c = (idx < NN) ? (int)(g_deg[idx] - 1.0f) : 0;
    int incl = c;
    #pragma unroll
    for (int o = 1; o < 32; o <<= 1) {
        int v = __shfl_up_sync(0xffffffffu, incl, o);
        if (l >= o) incl += v;
    }
    if (l == 31) wsum[w] = incl;
    __syncthreads();
    if (w == 0) {
        int v = wsum[l];
        #pragma unroll
        for (int o = 1; o < 32; o <<= 1) {
            int u = __shfl_up_sync(0xffffffffu, v, o);
            if (l >= o) v += u;
        }
        wsum[l] = v;
    }
    __syncthreads();
    int excl = (w ? wsum[w - 1] : 0) + incl - c;
    if (idx < NN) g_row_off[idx] = excl;
    if (t == 1023) g_blksum[b] = wsum[31];
}

__global__ void k_scan2() {
    int t = threadIdx.x, l = t & 31, w = t >> 5;
    __shared__ int ws[2];
    int v = (t < SCAN_NB) ? g_blksum[t] : 0;
    int incl = v;
    #pragma unroll
    for (int o = 1; o < 32; o <<= 1) {
        int u = __shfl_up_sync(0xffffffffu, incl, o);
        if (l >= o) incl += u;
    }
    if (l == 31) ws[w] = incl;
    __syncthreads();
    int inclusive = incl + (w == 1 ? ws[0] : 0);
    if (t < SCAN_NB) g_blkoff[t] = inclusive - v;
    if (t == SCAN_NB - 1) g_row_off[NN] = inclusive;
}

__global__ void k_scan3() {
    int b = blockIdx.x;
    int idx = b * 1024 + threadIdx.x;
    if (idx < NN) {
        int v = g_row_off[idx] + g_blkoff[b];
        g_row_off[idx] = v;
        g_cursor[idx]  = v;
    }
}

__global__ void k_fill(const int* __restrict__ src, const int* __restrict__ dst) {
    int e = blockIdx.x * blockDim.x + threadIdx.x;
    if (e < NE) {
        int p = atomicAdd(&g_cursor[dst[e]], 1);
        g_csr_src[p] = src[e];
    }
}

// ---------------------------------------------------------------------------
// Tensor-core GEMM, single fp16 term: acc += A*B.
// BM=128, BN=128, BK=32; 8 warps (4m x 2n), 32x64/warp; 3-stage cp.async.
// Output stored as fp16.
// ---------------------------------------------------------------------------
__device__ __forceinline__ uint32_t swzA(uint32_t a) { return a ^ ((a >> 3) & 0x30); }
__device__ __forceinline__ uint32_t swzB(uint32_t a) { return a ^ ((a >> 4) & 0x70); }

__device__ __forceinline__ void cpa16(uint32_t s, const void* g, int sz) {
    asm volatile("cp.async.cg.shared.global [%0], [%1], 16, %2;"
                 :: "r"(s), "l"(g), "r"(sz));
}
__device__ __forceinline__ void ldsm_x4(uint32_t* r, uint32_t addr) {
    asm volatile("ldmatrix.sync.aligned.m8n8.x4.shared.b16 {%0,%1,%2,%3}, [%4];"
                 : "=r"(r[0]), "=r"(r[1]), "=r"(r[2]), "=r"(r[3]) : "r"(addr));
}
__device__ __forceinline__ void ldsm_x4_t(uint32_t* r, uint32_t addr) {
    asm volatile("ldmatrix.sync.aligned.m8n8.x4.trans.shared.b16 {%0,%1,%2,%3}, [%4];"
                 : "=r"(r[0]), "=r"(r[1]), "=r"(r[2]), "=r"(r[3]) : "r"(addr));
}
__device__ __forceinline__ void mma16816(float* c, const uint32_t* a, const uint32_t* b) {
    asm volatile("mma.sync.aligned.m16n8k16.row.col.f32.f16.f16.f32 "
                 "{%0,%1,%2,%3}, {%4,%5,%6,%7}, {%8,%9}, {%0,%1,%2,%3};"
                 : "+f"(c[0]), "+f"(c[1]), "+f"(c[2]), "+f"(c[3])
                 : "r"(a[0]), "r"(a[1]), "r"(a[2]), "r"(a[3]), "r"(b[0]), "r"(b[1]));
}

__global__ __launch_bounds__(256, 2) void k_gemm(int l, const float* __restrict__ bias) {
    extern __shared__ __align__(128) unsigned char sm[];
    uint32_t sbase = (uint32_t)__cvta_generic_to_shared(sm);

    const __half* __restrict__ A = g_a;
    const __half* __restrict__ W = g_W + (size_t)l * DD * DD;

    int t = threadIdx.x;
    int lane = t & 31;
    int warp = t >> 5;
    int m0 = blockIdx.x * 128;
    int n0 = blockIdx.y * 128;
    int wm = (warp & 3) * 32;
    int wn = (warp >> 2) * 64;

    float acc[2][8][4];
    #pragma unroll
    for (int i = 0; i < 2; i++)
        #pragma unroll
        for (int j = 0; j < 8; j++)
            #pragma unroll
            for (int q = 0; q < 4; q++) acc[i][j][q] = 0.f;

    // cp.async load mappings
    int aRow = t >> 2;          // 0..63, +64*h
    int aU   = (t & 3);         // 16B unit within 64B row
    int bRow = t >> 3;          // 0..31
    int bU   = (t & 7);         // pair of 16B units within 256B row

    auto issue = [&](int kb) {
        uint32_t so = sbase + (uint32_t)(kb % NSTAGE) * STG_BYTES;
        #pragma unroll
        for (int h = 0; h < 2; h++) {
            int r = aRow + 64 * h;
            int gr = m0 + r;
            int sz = (gr < NN) ? 16 : 0;
            size_t gidx = (size_t)(gr < NN ? gr : 0) * DD + kb * 32 + aU * 8;
            uint32_t ad = swzA((uint32_t)r * 64 + aU * 16);
            cpa16(so + ad, &A[gidx], sz);
        }
        #pragma unroll
        for (int u = 0; u < 2; u++) {
            size_t gidx = (size_t)(kb * 32 + bRow) * DD + n0 + bU * 16 + u * 8;
            uint32_t bd = swzB((uint32_t)bRow * 256 + bU * 32 + u * 16);
            cpa16(so + 8192 + bd, &W[gidx], 16);
        }
    };

    const int NIT = DD / 32;  // 16
    issue(0);
    asm volatile("cp.async.commit_group;");
    issue(1);
    asm volatile("cp.async.commit_group;");

    for (int kb = 0; kb < NIT; kb++) {
        if (kb + 2 < NIT) {
            issue(kb + 2);
            asm volatile("cp.async.commit_group;");
            asm volatile("cp.async.wait_group 2;");
        } else if (kb + 2 == NIT) {
            asm volatile("cp.async.wait_group 1;");
        } else {
            asm volatile("cp.async.wait_group 0;");
        }
        __syncthreads();

        uint32_t so = sbase + (uint32_t)(kb % NSTAGE) * STG_BYTES;
        uint32_t sA = so, sB = so + 8192;

        #pragma unroll
        for (int ks = 0; ks < 2; ks++) {
            int k = ks * 16;
            uint32_t ah[2][4];
            #pragma unroll
            for (int mi = 0; mi < 2; mi++) {
                uint32_t ad = (uint32_t)(wm + mi * 16 + (lane & 15)) * 64
                            + (uint32_t)(k + 8 * (lane >> 4)) * 2;
                ldsm_x4(ah[mi], sA + swzA(ad));
            }
            #pragma unroll
            for (int nj = 0; nj < 4; nj++) {
                uint32_t bh[4];
                uint32_t bd = (uint32_t)(k + (lane & 15)) * 256
                            + (uint32_t)(wn + nj * 16 + 8 * (lane >> 4)) * 2;
                ldsm_x4_t(bh, sB + swzB(bd));
                #pragma unroll
                for (int mi = 0; mi < 2; mi++)
                    #pragma unroll
                    for (int hf = 0; hf < 2; hf++)
                        mma16816(acc[mi][nj * 2 + hf], ah[mi], bh + 2 * hf);
            }
        }
        __syncthreads();
    }

    // Epilogue: add bias, store fp16
    #pragma unroll
    for (int mi = 0; mi < 2; mi++) {
        #pragma unroll
        for (int nf = 0; nf < 8; nf++) {
            int row = m0 + wm + mi * 16 + (lane >> 2);
            int col = n0 + wn + nf * 8 + (lane & 3) * 2;
            float b0 = bias[col], b1 = bias[col + 1];
            float* c = acc[mi][nf];
            if (row < NN) {
                __half2 h = __floats2half2_rn(c[0] + b0, c[1] + b1);
                *reinterpret_cast<__half2*>(&g_ht[(size_t)row * DD + col]) = h;
            }
            if (row + 8 < NN) {
                __half2 h = __floats2half2_rn(c[2] + b0, c[3] + b1);
                *reinterpret_cast<__half2*>(&g_ht[(size_t)(row + 8) * DD + col]) = h;
            }
        }
    }
}

// ---------------------------------------------------------------------------
// FUSED: CSR gather-aggregate + self-loop + LayerNorm + ReLU.
// Gathers fp16 rows (16B = 8 halves per lane-chunk), accumulates in fp32.
// ---------------------------------------------------------------------------
__device__ __forceinline__ void acc_row8(float* a, uint4 v, float w) {
    float2 f0 = __half22float2(*reinterpret_cast<__half2*>(&v.x));
    float2 f1 = __half22float2(*reinterpret_cast<__half2*>(&v.y));
    float2 f2 = __half22float2(*reinterpret_cast<__half2*>(&v.z));
    float2 f3 = __half22float2(*reinterpret_cast<__half2*>(&v.w));
    a[0] += f0.x * w; a[1] += f0.y * w;
    a[2] += f1.x * w; a[3] += f1.y * w;
    a[4] += f2.x * w; a[5] += f2.y * w;
    a[6] += f3.x * w; a[7] += f3.y * w;
}

__global__ __launch_bounds__(256) void k_agg_ln(const float* __restrict__ gamma,
                                                const float* __restrict__ beta,
                                                float* __restrict__ out, int to_out) {
    int row = blockIdx.x * 8 + (threadIdx.x >> 5);
    if (row >= NN) return;
    int lane = threadIdx.x & 31;

    float isq_r = g_isq[row];

    float acc[2][8];
    {
        const uint4* ph = reinterpret_cast<const uint4*>(&g_ht[(size_t)row * DD]);
        #pragma unroll
        for (int j = 0; j < 2; j++) {
            #pragma unroll
            for (int q = 0; q < 8; q++) acc[j][q] = 0.f;
            acc_row8(acc[j], ph[lane + 32 * j], isq_r);
        }
    }

    int e  = g_row_off[row];
    int e1 = g_row_off[row + 1];
    for (; e + 1 < e1; e += 2) {
        int s0 = g_csr_src[e];
        int s1 = g_csr_src[e + 1];
        float w0 = g_isq[s0];
        float w1 = g_isq[s1];
        const uint4* p0 = reinterpret_cast<const uint4*>(&g_ht[(size_t)s0 * DD]);
        const uint4* p1 = reinterpret_cast<const uint4*>(&g_ht[(size_t)s1 * DD]);
        #pragma unroll
        for (int j = 0; j < 2; j++) {
            uint4 v0 = p0[lane + 32 * j];
            uint4 v1 = p1[lane + 32 * j];
            acc_row8(acc[j], v0, w0);
            acc_row8(acc[j], v1, w1);
        }
    }
    if (e < e1) {
        int s0 = g_csr_src[e];
        float w0 = g_isq[s0];
        const uint4* p0 = reinterpret_cast<const uint4*>(&g_ht[(size_t)s0 * DD]);
        #pragma unroll
        for (int j = 0; j < 2; j++)
            acc_row8(acc[j], p0[lane + 32 * j], w0);
    }

    float sum = 0.f, sq = 0.f;
    #pragma unroll
    for (int j = 0; j < 2; j++)
        #pragma unroll
        for (int q = 0; q < 8; q++) {
            acc[j][q] *= isq_r;
            sum += acc[j][q];
            sq  += acc[j][q] * acc[j][q];
        }
    #pragma unroll
    for (int o = 16; o > 0; o >>= 1) {
        sum += __shfl_xor_sync(0xffffffffu, sum, o);
        sq  += __shfl_xor_sync(0xffffffffu, sq, o);
    }
    float mean = sum * (1.0f / DD);
    float var  = sq * (1.0f / DD) - mean * mean;
    float rstd = rsqrtf(var + LN_EPS);

    #pragma unroll
    for (int j = 0; j < 2; j++) {
        int col = (lane + 32 * j) * 8;
        float r[8];
        #pragma unroll
        for (int q = 0; q < 8; q++)
            r[q] = fmaxf(gamma[col + q] * (acc[j][q] - mean) * rstd + beta[col + q], 0.f);
        if (to_out) {
            float4* po = reinterpret_cast<float4*>(&out[(size_t)row * DD + col]);
            po[0] = make_float4(r[0], r[1], r[2], r[3]);
            po[1] = make_float4(r[4], r[5], r[6], r[7]);
        } else {
            size_t pidx = ((size_t)row * DD + col) >> 1;
            #pragma unroll
            for (int q = 0; q < 4; q++)
                reinterpret_cast<__half2*>(g_a)[pidx + q] =
                    __floats2half2_rn(r[2 * q], r[2 * q + 1]);
        }
    }
}

// ---------------------------------------------------------------------------
extern "C" void kernel_launch(void* const* d_in, const int* in_sizes, int n_in,
                              void* d_out, int out_size) {
    const float* x      = (const float*)d_in[0];   // [NN, DD]
    const int*   edge   = (const int*)  d_in[1];   // [2, NE]
    const float* Ws     = (const float*)d_in[2];   // [NL, DD, DD]
    const float* bs     = (const float*)d_in[3];   // [NL, DD]
    const float* gammas = (const float*)d_in[4];   // [NL, DD]
    const float* betas  = (const float*)d_in[5];   // [NL, DD]
    float* out = (float*)d_out;

    const int* src = edge;
    const int* dst = edge + NE;

    cudaFuncSetAttribute(k_gemm, cudaFuncAttributeMaxDynamicSharedMemorySize, SMEM_TOT);

    // One-time conversions + graph preprocessing
    k_convW<<<NL * DD * DD / 2 / 256, 256>>>(Ws);
    k_convX<<<NN * DD / 2 / 256, 256>>>(x);
    k_deg_init<<<(NN + 255) / 256, 256>>>();
    k_deg_accum<<<(NE + 255) / 256, 256>>>(dst);
    k_isq<<<(NN + 255) / 256, 256>>>();
    k_scan1<<<SCAN_NB, 1024>>>();
    k_scan2<<<1, 64>>>();
    k_scan3<<<SCAN_NB, 1024>>>();
    k_fill<<<(NE + 255) / 256, 256>>>(src, dst);

    dim3 ggrid((NN + 127) / 128, DD / 128);
    for (int l = 0; l < NL; l++) {
        k_gemm<<<ggrid, 256, SMEM_TOT>>>(l, bs + l * DD);
        k_agg_ln<<<(NN + 7) / 8, 256>>>(gammas + l * DD, betas + l * DD,
                                        out, l == NL - 1 ? 1 : 0);
    }
}

// round 10
// speedup vs baseline: 5.4717x; 1.0375x over previous
#include <cuda_runtime.h>
#include <cuda_fp16.h>
#include <cstdint>

#define NN 50000
#define NE 800000
#define DD 512
#define NL 3
#define LN_EPS 1e-5f
#define SCAN_NB 49   // ceil(NN/1024)

// per-stage smem: A 16K | B 16K = 32 KB; 3 stages (BK=64)
#define STG_BYTES 32768
#define NSTAGE 3
#define SMEM_TOT (NSTAGE * STG_BYTES)

#define WPAIRS (NL * DD * DD / 2)
#define XPAIRS (NN * DD / 2)

// Scratch (device globals — no allocation allowed)
__device__ __half g_ht[NN * DD];           // GEMM output (fp16 storage)
__device__ __half g_a[NN * DD];            // layer input (fp16)
__device__ __half g_W[NL * DD * DD];       // weights (fp16)
__device__ float g_deg[NN];
__device__ float g_isq[NN];
__device__ int   g_row_off[NN + 1];
__device__ int   g_cursor[NN];
__device__ int   g_csr_src[NE];
__device__ int   g_blksum[SCAN_NB];
__device__ int   g_blkoff[SCAN_NB];

// ---------------------------------------------------------------------------
// Fused fp16 conversion: W pairs first, then X pairs.
// ---------------------------------------------------------------------------
__global__ void k_conv(const float* __restrict__ Ws, const float* __restrict__ x) {
    size_t i = (size_t)blockIdx.x * 256 + threadIdx.x;
    if (i < WPAIRS) {
        float2 v = reinterpret_cast<const float2*>(Ws)[i];
        reinterpret_cast<__half2*>(g_W)[i] = __floats2half2_rn(v.x, v.y);
    } else if (i < WPAIRS + XPAIRS) {
        size_t j = i - WPAIRS;
        float2 v = reinterpret_cast<const float2*>(x)[j];
        reinterpret_cast<__half2*>(g_a)[j] = __floats2half2_rn(v.x, v.y);
    }
}

// ---------------------------------------------------------------------------
// Degree / CSR preprocessing
// ---------------------------------------------------------------------------
__global__ void k_deg_init() {
    int i = blockIdx.x * blockDim.x + threadIdx.x;
    if (i < NN) g_deg[i] = 1.0f;
}
__global__ void k_deg_accum(const int* __restrict__ dst) {
    int e = blockIdx.x * blockDim.x + threadIdx.x;
    if (e < NE) atomicAdd(&g_deg[dst[e]], 1.0f);
}

// scan1 also computes isq = rsqrt(deg)
__global__ void k_scan1() {
    __shared__ int wsum[32];
    int b = blockIdx.x, t = threadIdx.x, w = t >> 5, l = t & 31;
    int idx = b * 1024 + t;
    float dg = (idx < NN) ? g_deg[idx] : 1.0f;
    if (idx < NN) g_isq[idx] = rsqrtf(dg);
    int c = (idx < NN) ? (int)(dg - 1.0f) : 0;
    int incl = c;
    #pragma unroll
    for (int o = 1; o < 32; o <<= 1) {
        int v = __shfl_up_sync(0xffffffffu, incl, o);
        if (l >= o) incl += v;
    }
    if (l == 31) wsum[w] = incl;
    __syncthreads();
    if (w == 0) {
        int v = wsum[l];
        #pragma unroll
        for (int o = 1; o < 32; o <<= 1) {
            int u = __shfl_up_sync(0xffffffffu, v, o);
            if (l >= o) v += u;
        }
        wsum[l] = v;
    }
    __syncthreads();
    int excl = (w ? wsum[w - 1] : 0) + incl - c;
    if (idx < NN) g_row_off[idx] = excl;
    if (t == 1023) g_blksum[b] = wsum[31];
}

__global__ void k_scan2() {
    int t = threadIdx.x, l = t & 31, w = t >> 5;
    __shared__ int ws[2];
    int v = (t < SCAN_NB) ? g_blksum[t] : 0;
    int incl = v;
    #pragma unroll
    for (int o = 1; o < 32; o <<= 1) {
        int u = __shfl_up_sync(0xffffffffu, incl, o);
        if (l >= o) incl += u;
    }
    if (l == 31) ws[w] = incl;
    __syncthreads();
    int inclusive = incl + (w == 1 ? ws[0] : 0);
    if (t < SCAN_NB) g_blkoff[t] = inclusive - v;
    if (t == SCAN_NB - 1) g_row_off[NN] = inclusive;
}

__global__ void k_scan3() {
    int b = blockIdx.x;
    int idx = b * 1024 + threadIdx.x;
    if (idx < NN) {
        int v = g_row_off[idx] + g_blkoff[b];
        g_row_off[idx] = v;
        g_cursor[idx]  = v;
    }
}

__global__ void k_fill(const int* __restrict__ src, const int* __restrict__ dst) {
    int e = blockIdx.x * blockDim.x + threadIdx.x;
    if (e < NE) {
        int p = atomicAdd(&g_cursor[dst[e]], 1);
        g_csr_src[p] = src[e];
    }
}

// ---------------------------------------------------------------------------
// Tensor-core GEMM, single fp16 term: acc += A*B.
// BM=128, BN=128, BK=64; 8 warps (4m x 2n), 32x64/warp; 3-stage cp.async.
// Output stored as fp16.
// ---------------------------------------------------------------------------
__device__ __forceinline__ uint32_t swzA(uint32_t a) { return a ^ ((a >> 3) & 0x70); }
__device__ __forceinline__ uint32_t swzB(uint32_t a) { return a ^ ((a >> 4) & 0x70); }

__device__ __forceinline__ void cpa16(uint32_t s, const void* g, int sz) {
    asm volatile("cp.async.cg.shared.global [%0], [%1], 16, %2;"
                 :: "r"(s), "l"(g), "r"(sz));
}
__device__ __forceinline__ void ldsm_x4(uint32_t* r, uint32_t addr) {
    asm volatile("ldmatrix.sync.aligned.m8n8.x4.shared.b16 {%0,%1,%2,%3}, [%4];"
                 : "=r"(r[0]), "=r"(r[1]), "=r"(r[2]), "=r"(r[3]) : "r"(addr));
}
__device__ __forceinline__ void ldsm_x4_t(uint32_t* r, uint32_t addr) {
    asm volatile("ldmatrix.sync.aligned.m8n8.x4.trans.shared.b16 {%0,%1,%2,%3}, [%4];"
                 : "=r"(r[0]), "=r"(r[1]), "=r"(r[2]), "=r"(r[3]) : "r"(addr));
}
__device__ __forceinline__ void mma16816(float* c, const uint32_t* a, const uint32_t* b) {
    asm volatile("mma.sync.aligned.m16n8k16.row.col.f32.f16.f16.f32 "
                 "{%0,%1,%2,%3}, {%4,%5,%6,%7}, {%8,%9}, {%0,%1,%2,%3};"
                 : "+f"(c[0]), "+f"(c[1]), "+f"(c[2]), "+f"(c[3])
                 : "r"(a[0]), "r"(a[1]), "r"(a[2]), "r"(a[3]), "r"(b[0]), "r"(b[1]));
}

__global__ __launch_bounds__(256, 2) void k_gemm(int l, const float* __restrict__ bias) {
    extern __shared__ __align__(128) unsigned char sm[];
    uint32_t sbase = (uint32_t)__cvta_generic_to_shared(sm);

    const __half* __restrict__ A = g_a;
    const __half* __restrict__ W = g_W + (size_t)l * DD * DD;

    int t = threadIdx.x;
    int lane = t & 31;
    int warp = t >> 5;
    int m0 = blockIdx.x * 128;
    int n0 = blockIdx.y * 128;
    int wm = (warp & 3) * 32;
    int wn = (warp >> 2) * 64;

    float acc[2][8][4];
    #pragma unroll
    for (int i = 0; i < 2; i++)
        #pragma unroll
        for (int j = 0; j < 8; j++)
            #pragma unroll
            for (int q = 0; q < 4; q++) acc[i][j][q] = 0.f;

    // cp.async load mappings: A tile 128 rows x 128B; B tile 64 rows x 256B.
    auto issue = [&](int kb) {
        uint32_t so = sbase + (uint32_t)(kb % NSTAGE) * STG_BYTES;
        #pragma unroll
        for (int i = 0; i < 4; i++) {
            int c = t + 256 * i;
            int row = c >> 3, u = c & 7;
            int gr = m0 + row;
            int sz = (gr < NN) ? 16 : 0;
            size_t gidx = (size_t)(gr < NN ? gr : 0) * DD + kb * 64 + u * 8;
            cpa16(so + swzA((uint32_t)row * 128 + u * 16), &A[gidx], sz);
        }
        #pragma unroll
        for (int i = 0; i < 4; i++) {
            int c = t + 256 * i;
            int row = c >> 4, u = c & 15;
            size_t gidx = (size_t)(kb * 64 + row) * DD + n0 + u * 8;
            cpa16(so + 16384 + swzB((uint32_t)row * 256 + u * 16), &W[gidx], 16);
        }
    };

    const int NIT = DD / 64;  // 8
    issue(0);
    asm volatile("cp.async.commit_group;");
    issue(1);
    asm volatile("cp.async.commit_group;");

    for (int kb = 0; kb < NIT; kb++) {
        if (kb + 2 < NIT) {
            issue(kb + 2);
            asm volatile("cp.async.commit_group;");
            asm volatile("cp.async.wait_group 2;");
        } else if (kb + 2 == NIT) {
            asm volatile("cp.async.wait_group 1;");
        } else {
            asm volatile("cp.async.wait_group 0;");
        }
        __syncthreads();

        uint32_t so = sbase + (uint32_t)(kb % NSTAGE) * STG_BYTES;
        uint32_t sA = so, sB = so + 16384;

        #pragma unroll
        for (int ks = 0; ks < 4; ks++) {
            int k = ks * 16;
            uint32_t ah[2][4];
            #pragma unroll
            for (int mi = 0; mi < 2; mi++) {
                uint32_t ad = (uint32_t)(wm + mi * 16 + (lane & 15)) * 128
                            + (uint32_t)(k + 8 * (lane >> 4)) * 2;
                ldsm_x4(ah[mi], sA + swzA(ad));
            }
            #pragma unroll
            for (int nj = 0; nj < 4; nj++) {
                uint32_t bh[4];
                uint32_t bd = (uint32_t)(k + (lane & 15)) * 256
                            + (uint32_t)(wn + nj * 16 + 8 * (lane >> 4)) * 2;
                ldsm_x4_t(bh, sB + swzB(bd));
                #pragma unroll
                for (int mi = 0; mi < 2; mi++)
                    #pragma unroll
                    for (int hf = 0; hf < 2; hf++)
                        mma16816(acc[mi][nj * 2 + hf], ah[mi], bh + 2 * hf);
            }
        }
        __syncthreads();
    }

    // Epilogue: add bias, store fp16
    #pragma unroll
    for (int mi = 0; mi < 2; mi++) {
        #pragma unroll
        for (int nf = 0; nf < 8; nf++) {
            int row = m0 + wm + mi * 16 + (lane >> 2);
            int col = n0 + wn + nf * 8 + (lane & 3) * 2;
            float b0 = bias[col], b1 = bias[col + 1];
            float* c = acc[mi][nf];
            if (row < NN) {
                __half2 h = __floats2half2_rn(c[0] + b0, c[1] + b1);
                *reinterpret_cast<__half2*>(&g_ht[(size_t)row * DD + col]) = h;
            }
            if (row + 8 < NN) {
                __half2 h = __floats2half2_rn(c[2] + b0, c[3] + b1);
                *reinterpret_cast<__half2*>(&g_ht[(size_t)(row + 8) * DD + col]) = h;
            }
        }
    }
}

// ---------------------------------------------------------------------------
// FUSED: CSR gather-aggregate + self-loop + LayerNorm + ReLU.
// Gathers fp16 rows (16B = 8 halves per lane-chunk), accumulates in fp32.
// ---------------------------------------------------------------------------
__device__ __forceinline__ void acc_row8(float* a, uint4 v, float w) {
    float2 f0 = __half22float2(*reinterpret_cast<__half2*>(&v.x));
    float2 f1 = __half22float2(*reinterpret_cast<__half2*>(&v.y));
    float2 f2 = __half22float2(*reinterpret_cast<__half2*>(&v.z));
    float2 f3 = __half22float2(*reinterpret_cast<__half2*>(&v.w));
    a[0] += f0.x * w; a[1] += f0.y * w;
    a[2] += f1.x * w; a[3] += f1.y * w;
    a[4] += f2.x * w; a[5] += f2.y * w;
    a[6] += f3.x * w; a[7] += f3.y * w;
}

__global__ __launch_bounds__(256) void k_agg_ln(const float* __restrict__ gamma,
                                                const float* __restrict__ beta,
                                                float* __restrict__ out, int to_out) {
    int row = blockIdx.x * 8 + (threadIdx.x >> 5);
    if (row >= NN) return;
    int lane = threadIdx.x & 31;

    float isq_r = g_isq[row];

    float acc[2][8];
    {
        const uint4* ph = reinterpret_cast<const uint4*>(&g_ht[(size_t)row * DD]);
        #pragma unroll
        for (int j = 0; j < 2; j++) {
            #pragma unroll
            for (int q = 0; q < 8; q++) acc[j][q] = 0.f;
            acc_row8(acc[j], ph[lane + 32 * j], isq_r);
        }
    }

    int e  = g_row_off[row];
    int e1 = g_row_off[row + 1];
    for (; e + 1 < e1; e += 2) {
        int s0 = g_csr_src[e];
        int s1 = g_csr_src[e + 1];
        float w0 = g_isq[s0];
        float w1 = g_isq[s1];
        const uint4* p0 = reinterpret_cast<const uint4*>(&g_ht[(size_t)s0 * DD]);
        const uint4* p1 = reinterpret_cast<const uint4*>(&g_ht[(size_t)s1 * DD]);
        #pragma unroll
        for (int j = 0; j < 2; j++) {
            uint4 v0 = p0[lane + 32 * j];
            uint4 v1 = p1[lane + 32 * j];
            acc_row8(acc[j], v0, w0);
            acc_row8(acc[j], v1, w1);
        }
    }
    if (e < e1) {
        int s0 = g_csr_src[e];
        float w0 = g_isq[s0];
        const uint4* p0 = reinterpret_cast<const uint4*>(&g_ht[(size_t)s0 * DD]);
        #pragma unroll
        for (int j = 0; j < 2; j++)
            acc_row8(acc[j], p0[lane + 32 * j], w0);
    }

    float sum = 0.f, sq = 0.f;
    #pragma unroll
    for (int j = 0; j < 2; j++)
        #pragma unroll
        for (int q = 0; q < 8; q++) {
            acc[j][q] *= isq_r;
            sum += acc[j][q];
            sq  += acc[j][q] * acc[j][q];
        }
    #pragma unroll
    for (int o = 16; o > 0; o >>= 1) {
        sum += __shfl_xor_sync(0xffffffffu, sum, o);
        sq  += __shfl_xor_sync(0xffffffffu, sq, o);
    }
    float mean = sum * (1.0f / DD);
    float var  = sq * (1.0f / DD) - mean * mean;
    float rstd = rsqrtf(var + LN_EPS);

    #pragma unroll
    for (int j = 0; j < 2; j++) {
        int col = (lane + 32 * j) * 8;
        float r[8];
        #pragma unroll
        for (int q = 0; q < 8; q++)
            r[q] = fmaxf(gamma[col + q] * (acc[j][q] - mean) * rstd + beta[col + q], 0.f);
        if (to_out) {
            float4* po = reinterpret_cast<float4*>(&out[(size_t)row * DD + col]);
            po[0] = make_float4(r[0], r[1], r[2], r[3]);
            po[1] = make_float4(r[4], r[5], r[6], r[7]);
        } else {
            size_t pidx = ((size_t)row * DD + col) >> 1;
            #pragma unroll
            for (int q = 0; q < 4; q++)
                reinterpret_cast<__half2*>(g_a)[pidx + q] =
                    __floats2half2_rn(r[2 * q], r[2 * q + 1]);
        }
    }
}

// ---------------------------------------------------------------------------
extern "C" void kernel_launch(void* const* d_in, const int* in_sizes, int n_in,
                              void* d_out, int out_size) {
    const float* x      = (const float*)d_in[0];   // [NN, DD]
    const int*   edge   = (const int*)  d_in[1];   // [2, NE]
    const float* Ws     = (const float*)d_in[2];   // [NL, DD, DD]
    const float* bs     = (const float*)d_in[3];   // [NL, DD]
    const float* gammas = (const float*)d_in[4];   // [NL, DD]
    const float* betas  = (const float*)d_in[5];   // [NL, DD]
    float* out = (float*)d_out;

    const int* src = edge;
    const int* dst = edge + NE;

    cudaFuncSetAttribute(k_gemm, cudaFuncAttributeMaxDynamicSharedMemorySize, SMEM_TOT);

    // One-time conversions + graph preprocessing (7 launches)
    k_conv<<<(WPAIRS + XPAIRS + 255) / 256, 256>>>(Ws, x);
    k_deg_init<<<(NN + 255) / 256, 256>>>();
    k_deg_accum<<<(NE + 255) / 256, 256>>>(dst);
    k_scan1<<<SCAN_NB, 1024>>>();
    k_scan2<<<1, 64>>>();
    k_scan3<<<SCAN_NB, 1024>>>();
    k_fill<<<(NE + 255) / 256, 256>>>(src, dst);

    dim3 ggrid((NN + 127) / 128, DD / 128);
    for (int l = 0; l < NL; l++) {
        k_gemm<<<ggrid, 256, SMEM_TOT>>>(l, bs + l * DD);
        k_agg_ln<<<(NN + 7) / 8, 256>>>(gammas + l * DD, betas + l * DD,
                                        out, l == NL - 1 ? 1 : 0);
    }
}

// round 11
// speedup vs baseline: 5.5476x; 1.0139x over previous
#include <cuda_runtime.h>
#include <cuda_fp16.h>
#include <cstdint>

#define NN 50000
#define NE 800000
#define DD 512
#define NL 3
#define LN_EPS 1e-5f
#define SCAN_NB 49   // ceil(NN/1024)

// per-stage smem: A 16K | B 16K = 32 KB; 3 stages (BK=64)
#define STG_BYTES 32768
#define NSTAGE 3
#define SMEM_TOT (NSTAGE * STG_BYTES)

#define WPAIRS (NL * DD * DD / 2)
#define XPAIRS (NN * DD / 2)

// Scratch (device globals — no allocation allowed)
__device__ __half g_ht[NN * DD];           // GEMM output (fp16 storage)
__device__ __half g_a[NN * DD];            // layer input (fp16)
__device__ __half g_W[NL * DD * DD];       // weights (fp16)
__device__ float g_deg[NN];
__device__ float g_isq[NN];
__device__ int   g_row_off[NN + 1];
__device__ int   g_cursor[NN];
__device__ int   g_csr_src[NE];
__device__ int   g_blksum[SCAN_NB];
__device__ int   g_blkoff[SCAN_NB];

// ---------------------------------------------------------------------------
// Fused fp16 conversion: W pairs first, then X pairs.
// ---------------------------------------------------------------------------
__global__ void k_conv(const float* __restrict__ Ws, const float* __restrict__ x) {
    size_t i = (size_t)blockIdx.x * 256 + threadIdx.x;
    if (i < WPAIRS) {
        float2 v = reinterpret_cast<const float2*>(Ws)[i];
        reinterpret_cast<__half2*>(g_W)[i] = __floats2half2_rn(v.x, v.y);
    } else if (i < WPAIRS + XPAIRS) {
        size_t j = i - WPAIRS;
        float2 v = reinterpret_cast<const float2*>(x)[j];
        reinterpret_cast<__half2*>(g_a)[j] = __floats2half2_rn(v.x, v.y);
    }
}

// ---------------------------------------------------------------------------
// Degree / CSR preprocessing (runs on the side stream, overlapped with
// k_conv + first GEMM; only k_agg_ln depends on it)
// ---------------------------------------------------------------------------
__global__ void k_deg_init() {
    int i = blockIdx.x * blockDim.x + threadIdx.x;
    if (i < NN) g_deg[i] = 1.0f;
}
__global__ void k_deg_accum(const int* __restrict__ dst) {
    int e = blockIdx.x * blockDim.x + threadIdx.x;
    if (e < NE) atomicAdd(&g_deg[dst[e]], 1.0f);
}

// scan1 also computes isq = rsqrt(deg)
__global__ void k_scan1() {
    __shared__ int wsum[32];
    int b = blockIdx.x, t = threadIdx.x, w = t >> 5, l = t & 31;
    int idx = b * 1024 + t;
    float dg = (idx < NN) ? g_deg[idx] : 1.0f;
    if (idx < NN) g_isq[idx] = rsqrtf(dg);
    int c = (idx < NN) ? (int)(dg - 1.0f) : 0;
    int incl = c;
    #pragma unroll
    for (int o = 1; o < 32; o <<= 1) {
        int v = __shfl_up_sync(0xffffffffu, incl, o);
        if (l >= o) incl += v;
    }
    if (l == 31) wsum[w] = incl;
    __syncthreads();
    if (w == 0) {
        int v = wsum[l];
        #pragma unroll
        for (int o = 1; o < 32; o <<= 1) {
            int u = __shfl_up_sync(0xffffffffu, v, o);
            if (l >= o) v += u;
        }
        wsum[l] = v;
    }
    __syncthreads();
    int excl = (w ? wsum[w - 1] : 0) + incl - c;
    if (idx < NN) g_row_off[idx] = excl;
    if (t == 1023) g_blksum[b] = wsum[31];
}

__global__ void k_scan2() {
    int t = threadIdx.x, l = t & 31, w = t >> 5;
    __shared__ int ws[2];
    int v = (t < SCAN_NB) ? g_blksum[t] : 0;
    int incl = v;
    #pragma unroll
    for (int o = 1; o < 32; o <<= 1) {
        int u = __shfl_up_sync(0xffffffffu, incl, o);
        if (l >= o) incl += u;
    }
    if (l == 31) ws[w] = incl;
    __syncthreads();
    int inclusive = incl + (w == 1 ? ws[0] : 0);
    if (t < SCAN_NB) g_blkoff[t] = inclusive - v;
    if (t == SCAN_NB - 1) g_row_off[NN] = inclusive;
}

__global__ void k_scan3() {
    int b = blockIdx.x;
    int idx = b * 1024 + threadIdx.x;
    if (idx < NN) {
        int v = g_row_off[idx] + g_blkoff[b];
        g_row_off[idx] = v;
        g_cursor[idx]  = v;
    }
}

__global__ void k_fill(const int* __restrict__ src, const int* __restrict__ dst) {
    int e = blockIdx.x * blockDim.x + threadIdx.x;
    if (e < NE) {
        int p = atomicAdd(&g_cursor[dst[e]], 1);
        g_csr_src[p] = src[e];
    }
}

// ---------------------------------------------------------------------------
// Tensor-core GEMM, single fp16 term: acc += A*B.
// BM=128, BN=128, BK=64; 8 warps (4m x 2n), 32x64/warp; 3-stage cp.async.
// Output stored as fp16.
// ---------------------------------------------------------------------------
__device__ __forceinline__ uint32_t swzA(uint32_t a) { return a ^ ((a >> 3) & 0x70); }
__device__ __forceinline__ uint32_t swzB(uint32_t a) { return a ^ ((a >> 4) & 0x70); }

__device__ __forceinline__ void cpa16(uint32_t s, const void* g, int sz) {
    asm volatile("cp.async.cg.shared.global [%0], [%1], 16, %2;"
                 :: "r"(s), "l"(g), "r"(sz));
}
__device__ __forceinline__ void ldsm_x4(uint32_t* r, uint32_t addr) {
    asm volatile("ldmatrix.sync.aligned.m8n8.x4.shared.b16 {%0,%1,%2,%3}, [%4];"
                 : "=r"(r[0]), "=r"(r[1]), "=r"(r[2]), "=r"(r[3]) : "r"(addr));
}
__device__ __forceinline__ void ldsm_x4_t(uint32_t* r, uint32_t addr) {
    asm volatile("ldmatrix.sync.aligned.m8n8.x4.trans.shared.b16 {%0,%1,%2,%3}, [%4];"
                 : "=r"(r[0]), "=r"(r[1]), "=r"(r[2]), "=r"(r[3]) : "r"(addr));
}
__device__ __forceinline__ void mma16816(float* c, const uint32_t* a, const uint32_t* b) {
    asm volatile("mma.sync.aligned.m16n8k16.row.col.f32.f16.f16.f32 "
                 "{%0,%1,%2,%3}, {%4,%5,%6,%7}, {%8,%9}, {%0,%1,%2,%3};"
                 : "+f"(c[0]), "+f"(c[1]), "+f"(c[2]), "+f"(c[3])
                 : "r"(a[0]), "r"(a[1]), "r"(a[2]), "r"(a[3]), "r"(b[0]), "r"(b[1]));
}

__global__ __launch_bounds__(256, 2) void k_gemm(int l, const float* __restrict__ bias) {
    extern __shared__ __align__(128) unsigned char sm[];
    uint32_t sbase = (uint32_t)__cvta_generic_to_shared(sm);

    const __half* __restrict__ A = g_a;
    const __half* __restrict__ W = g_W + (size_t)l * DD * DD;

    int t = threadIdx.x;
    int lane = t & 31;
    int warp = t >> 5;
    int m0 = blockIdx.x * 128;
    int n0 = blockIdx.y * 128;
    int wm = (warp & 3) * 32;
    int wn = (warp >> 2) * 64;

    float acc[2][8][4];
    #pragma unroll
    for (int i = 0; i < 2; i++)
        #pragma unroll
        for (int j = 0; j < 8; j++)
            #pragma unroll
            for (int q = 0; q < 4; q++) acc[i][j][q] = 0.f;

    // cp.async load mappings: A tile 128 rows x 128B; B tile 64 rows x 256B.
    auto issue = [&](int kb) {
        uint32_t so = sbase + (uint32_t)(kb % NSTAGE) * STG_BYTES;
        #pragma unroll
        for (int i = 0; i < 4; i++) {
            int c = t + 256 * i;
            int row = c >> 3, u = c & 7;
            int gr = m0 + row;
            int sz = (gr < NN) ? 16 : 0;
            size_t gidx = (size_t)(gr < NN ? gr : 0) * DD + kb * 64 + u * 8;
            cpa16(so + swzA((uint32_t)row * 128 + u * 16), &A[gidx], sz);
        }
        #pragma unroll
        for (int i = 0; i < 4; i++) {
            int c = t + 256 * i;
            int row = c >> 4, u = c & 15;
            size_t gidx = (size_t)(kb * 64 + row) * DD + n0 + u * 8;
            cpa16(so + 16384 + swzB((uint32_t)row * 256 + u * 16), &W[gidx], 16);
        }
    };

    const int NIT = DD / 64;  // 8
    issue(0);
    asm volatile("cp.async.commit_group;");
    issue(1);
    asm volatile("cp.async.commit_group;");

    for (int kb = 0; kb < NIT; kb++) {
        if (kb + 2 < NIT) {
            issue(kb + 2);
            asm volatile("cp.async.commit_group;");
            asm volatile("cp.async.wait_group 2;");
        } else if (kb + 2 == NIT) {
            asm volatile("cp.async.wait_group 1;");
        } else {
            asm volatile("cp.async.wait_group 0;");
        }
        __syncthreads();

        uint32_t so = sbase + (uint32_t)(kb % NSTAGE) * STG_BYTES;
        uint32_t sA = so, sB = so + 16384;

        #pragma unroll
        for (int ks = 0; ks < 4; ks++) {
            int k = ks * 16;
            uint32_t ah[2][4];
            #pragma unroll
            for (int mi = 0; mi < 2; mi++) {
                uint32_t ad = (uint32_t)(wm + mi * 16 + (lane & 15)) * 128
                            + (uint32_t)(k + 8 * (lane >> 4)) * 2;
                ldsm_x4(ah[mi], sA + swzA(ad));
            }
            #pragma unroll
            for (int nj = 0; nj < 4; nj++) {
                uint32_t bh[4];
                uint32_t bd = (uint32_t)(k + (lane & 15)) * 256
                            + (uint32_t)(wn + nj * 16 + 8 * (lane >> 4)) * 2;
                ldsm_x4_t(bh, sB + swzB(bd));
                #pragma unroll
                for (int mi = 0; mi < 2; mi++)
                    #pragma unroll
                    for (int hf = 0; hf < 2; hf++)
                        mma16816(acc[mi][nj * 2 + hf], ah[mi], bh + 2 * hf);
            }
        }
        __syncthreads();
    }

    // Epilogue: add bias, store fp16
    #pragma unroll
    for (int mi = 0; mi < 2; mi++) {
        #pragma unroll
        for (int nf = 0; nf < 8; nf++) {
            int row = m0 + wm + mi * 16 + (lane >> 2);
            int col = n0 + wn + nf * 8 + (lane & 3) * 2;
            float b0 = bias[col], b1 = bias[col + 1];
            float* c = acc[mi][nf];
            if (row < NN) {
                __half2 h = __floats2half2_rn(c[0] + b0, c[1] + b1);
                *reinterpret_cast<__half2*>(&g_ht[(size_t)row * DD + col]) = h;
            }
            if (row + 8 < NN) {
                __half2 h = __floats2half2_rn(c[2] + b0, c[3] + b1);
                *reinterpret_cast<__half2*>(&g_ht[(size_t)(row + 8) * DD + col]) = h;
            }
        }
    }
}

// ---------------------------------------------------------------------------
// FUSED: CSR gather-aggregate + self-loop + LayerNorm + ReLU.
// Gathers fp16 rows (16B = 8 halves per lane-chunk), accumulates in fp32.
// ---------------------------------------------------------------------------
__device__ __forceinline__ void acc_row8(float* a, uint4 v, float w) {
    float2 f0 = __half22float2(*reinterpret_cast<__half2*>(&v.x));
    float2 f1 = __half22float2(*reinterpret_cast<__half2*>(&v.y));
    float2 f2 = __half22float2(*reinterpret_cast<__half2*>(&v.z));
    float2 f3 = __half22float2(*reinterpret_cast<__half2*>(&v.w));
    a[0] += f0.x * w; a[1] += f0.y * w;
    a[2] += f1.x * w; a[3] += f1.y * w;
    a[4] += f2.x * w; a[5] += f2.y * w;
    a[6] += f3.x * w; a[7] += f3.y * w;
}

__global__ __launch_bounds__(256) void k_agg_ln(const float* __restrict__ gamma,
                                                const float* __restrict__ beta,
                                                float* __restrict__ out, int to_out) {
    int row = blockIdx.x * 8 + (threadIdx.x >> 5);
    if (row >= NN) return;
    int lane = threadIdx.x & 31;

    float isq_r = g_isq[row];

    float acc[2][8];
    {
        const uint4* ph = reinterpret_cast<const uint4*>(&g_ht[(size_t)row * DD]);
        #pragma unroll
        for (int j = 0; j < 2; j++) {
            #pragma unroll
            for (int q = 0; q < 8; q++) acc[j][q] = 0.f;
            acc_row8(acc[j], ph[lane + 32 * j], isq_r);
        }
    }

    int e  = g_row_off[row];
    int e1 = g_row_off[row + 1];
    for (; e + 1 < e1; e += 2) {
        int s0 = g_csr_src[e];
        int s1 = g_csr_src[e + 1];
        float w0 = g_isq[s0];
        float w1 = g_isq[s1];
        const uint4* p0 = reinterpret_cast<const uint4*>(&g_ht[(size_t)s0 * DD]);
        const uint4* p1 = reinterpret_cast<const uint4*>(&g_ht[(size_t)s1 * DD]);
        #pragma unroll
        for (int j = 0; j < 2; j++) {
            uint4 v0 = p0[lane + 32 * j];
            uint4 v1 = p1[lane + 32 * j];
            acc_row8(acc[j], v0, w0);
            acc_row8(acc[j], v1, w1);
        }
    }
    if (e < e1) {
        int s0 = g_csr_src[e];
        float w0 = g_isq[s0];
        const uint4* p0 = reinterpret_cast<const uint4*>(&g_ht[(size_t)s0 * DD]);
        #pragma unroll
        for (int j = 0; j < 2; j++)
            acc_row8(acc[j], p0[lane + 32 * j], w0);
    }

    float sum = 0.f, sq = 0.f;
    #pragma unroll
    for (int j = 0; j < 2; j++)
        #pragma unroll
        for (int q = 0; q < 8; q++) {
            acc[j][q] *= isq_r;
            sum += acc[j][q];
            sq  += acc[j][q] * acc[j][q];
        }
    #pragma unroll
    for (int o = 16; o > 0; o >>= 1) {
        sum += __shfl_xor_sync(0xffffffffu, sum, o);
        sq  += __shfl_xor_sync(0xffffffffu, sq, o);
    }
    float mean = sum * (1.0f / DD);
    float var  = sq * (1.0f / DD) - mean * mean;
    float rstd = rsqrtf(var + LN_EPS);

    #pragma unroll
    for (int j = 0; j < 2; j++) {
        int col = (lane + 32 * j) * 8;
        float r[8];
        #pragma unroll
        for (int q = 0; q < 8; q++)
            r[q] = fmaxf(gamma[col + q] * (acc[j][q] - mean) * rstd + beta[col + q], 0.f);
        if (to_out) {
            float4* po = reinterpret_cast<float4*>(&out[(size_t)row * DD + col]);
            po[0] = make_float4(r[0], r[1], r[2], r[3]);
            po[1] = make_float4(r[4], r[5], r[6], r[7]);
        } else {
            size_t pidx = ((size_t)row * DD + col) >> 1;
            #pragma unroll
            for (int q = 0; q < 4; q++)
                reinterpret_cast<__half2*>(g_a)[pidx + q] =
                    __floats2half2_rn(r[2 * q], r[2 * q + 1]);
        }
    }
}

// ---------------------------------------------------------------------------
extern "C" void kernel_launch(void* const* d_in, const int* in_sizes, int n_in,
                              void* d_out, int out_size) {
    const float* x      = (const float*)d_in[0];   // [NN, DD]
    const int*   edge   = (const int*)  d_in[1];   // [2, NE]
    const float* Ws     = (const float*)d_in[2];   // [NL, DD, DD]
    const float* bs     = (const float*)d_in[3];   // [NL, DD]
    const float* gammas = (const float*)d_in[4];   // [NL, DD]
    const float* betas  = (const float*)d_in[5];   // [NL, DD]
    float* out = (float*)d_out;

    const int* src = edge;
    const int* dst = edge + NE;

    cudaFuncSetAttribute(k_gemm, cudaFuncAttributeMaxDynamicSharedMemorySize, SMEM_TOT);

    // Fork: CSR preprocessing runs on a side stream, overlapped with
    // k_conv + first GEMM. Joined before the first k_agg_ln (its only consumer).
    cudaStream_t s;
    cudaStreamCreateWithFlags(&s, cudaStreamNonBlocking);
    cudaEvent_t eFork, eJoin;
    cudaEventCreateWithFlags(&eFork, cudaEventDisableTiming);
    cudaEventCreateWithFlags(&eJoin, cudaEventDisableTiming);

    cudaEventRecord(eFork, 0);
    cudaStreamWaitEvent(s, eFork, 0);
    k_deg_init<<<(NN + 255) / 256, 256, 0, s>>>();
    k_deg_accum<<<(NE + 255) / 256, 256, 0, s>>>(dst);
    k_scan1<<<SCAN_NB, 1024, 0, s>>>();
    k_scan2<<<1, 64, 0, s>>>();
    k_scan3<<<SCAN_NB, 1024, 0, s>>>();
    k_fill<<<(NE + 255) / 256, 256, 0, s>>>(src, dst);
    cudaEventRecord(eJoin, s);

    // Main chain
    k_conv<<<(WPAIRS + XPAIRS + 255) / 256, 256>>>(Ws, x);

    dim3 ggrid((NN + 127) / 128, DD / 128);
    k_gemm<<<ggrid, 256, SMEM_TOT>>>(0, bs);
    cudaStreamWaitEvent(0, eJoin, 0);   // CSR must be ready from here on
    k_agg_ln<<<(NN + 7) / 8, 256>>>(gammas, betas, out, 0);
    for (int l = 1; l < NL; l++) {
        k_gemm<<<ggrid, 256, SMEM_TOT>>>(l, bs + l * DD);
        k_agg_ln<<<(NN + 7) / 8, 256>>>(gammas + l * DD, betas + l * DD,
                                        out, l == NL - 1 ? 1 : 0);
    }

    cudaEventDestroy(eFork);
    cudaEventDestroy(eJoin);
    cudaStreamDestroy(s);
}